// round 1
// baseline (speedup 1.0000x reference)
#include <cuda_runtime.h>
#include <cstddef>

// ---------------------------------------------------------------------------
// MultiHeadMemory: H=16 heads, M=1024 memory slots, D=512, O=512, N=16384
//
// Pipeline:
//  1. key_logits[h] = mems[h] @ Wk[h]^T + bk[h]   (NT gemm)  -> g_memkey
//  2. mem_val[h]    = mems[h] @ Wv[h]^T + bv[h]   (NT gemm)  -> g_memval
//  3. softmax rows of g_memkey (len 512), in place
//  4. att[h] = k @ mem_key[h]^T                   (NT gemm)  -> g_att (1 GiB)
//  5. softmax rows of g_att (len 1024), in place  (exp computed exactly once)
//  6. out_h[h] = att_w[h] @ mem_val[h]            (NN gemm)  -> g_X[n, h*512+o]
//  7. out = g_X @ Wf^T + bf                       (NT gemm)  -> d_out
// ---------------------------------------------------------------------------

#define H_  16
#define M_  1024
#define D_  512
#define O_  512
#define N_  16384

#define BM 64
#define BN 64
#define BK 16

// Scratch (static device globals; allocation-free kernel_launch)
__device__ float g_memkey[(size_t)H_ * M_ * O_];            // 32 MB
__device__ float g_memval[(size_t)H_ * M_ * O_];            // 32 MB
__device__ float g_att[(size_t)H_ * N_ * M_];               // 1 GiB
__device__ float g_X[(size_t)N_ * (H_ * O_)];               // 512 MB

// ---------------------------------------------------------------------------
// Warp reductions
// ---------------------------------------------------------------------------
__device__ __forceinline__ float warpMax(float v) {
#pragma unroll
    for (int o = 16; o > 0; o >>= 1) v = fmaxf(v, __shfl_xor_sync(0xffffffffu, v, o));
    return v;
}
__device__ __forceinline__ float warpSum(float v) {
#pragma unroll
    for (int o = 16; o > 0; o >>= 1) v += __shfl_xor_sync(0xffffffffu, v, o);
    return v;
}

// ---------------------------------------------------------------------------
// GEMM NT: C[M,N] = A[M,K] * B[N,K]^T (+ bias[N]), per-head strides via z.
// lda = K, ldb = K, ldc = N. 64x64 tile, 256 threads, 4x4 micro-tile.
// ---------------------------------------------------------------------------
__global__ void __launch_bounds__(256) gemm_nt(
    const float* __restrict__ A, long long aStride,
    const float* __restrict__ B, long long bStride,
    float* __restrict__ C, long long cStride,
    const float* __restrict__ bias, long long biasStride,
    int M, int N, int K)
{
    const int h = blockIdx.z;
    A += (long long)h * aStride;
    B += (long long)h * bStride;
    C += (long long)h * cStride;
    if (bias) bias += (long long)h * biasStride;

    __shared__ __align__(16) float As[BK][BM];
    __shared__ __align__(16) float Bs[BK][BN];

    const int tid = threadIdx.x;
    const int tx = tid & 15;
    const int ty = tid >> 4;
    const int m0 = blockIdx.x * BM;
    const int n0 = blockIdx.y * BN;

    const int aRow = tid >> 2;        // 0..63
    const int aCol = (tid & 3) * 4;   // 0,4,8,12

    float acc[4][4] = {};

    for (int k0 = 0; k0 < K; k0 += BK) {
        const float4 av = *reinterpret_cast<const float4*>(
            A + (long long)(m0 + aRow) * K + k0 + aCol);
        const float4 bv = *reinterpret_cast<const float4*>(
            B + (long long)(n0 + aRow) * K + k0 + aCol);
        As[aCol + 0][aRow] = av.x; As[aCol + 1][aRow] = av.y;
        As[aCol + 2][aRow] = av.z; As[aCol + 3][aRow] = av.w;
        Bs[aCol + 0][aRow] = bv.x; Bs[aCol + 1][aRow] = bv.y;
        Bs[aCol + 2][aRow] = bv.z; Bs[aCol + 3][aRow] = bv.w;
        __syncthreads();

#pragma unroll
        for (int kk = 0; kk < BK; ++kk) {
            const float4 a = *reinterpret_cast<const float4*>(&As[kk][ty * 4]);
            const float4 b = *reinterpret_cast<const float4*>(&Bs[kk][tx * 4]);
            acc[0][0] += a.x * b.x; acc[0][1] += a.x * b.y; acc[0][2] += a.x * b.z; acc[0][3] += a.x * b.w;
            acc[1][0] += a.y * b.x; acc[1][1] += a.y * b.y; acc[1][2] += a.y * b.z; acc[1][3] += a.y * b.w;
            acc[2][0] += a.z * b.x; acc[2][1] += a.z * b.y; acc[2][2] += a.z * b.z; acc[2][3] += a.z * b.w;
            acc[3][0] += a.w * b.x; acc[3][1] += a.w * b.y; acc[3][2] += a.w * b.z; acc[3][3] += a.w * b.w;
        }
        __syncthreads();
    }

    float4 bb = make_float4(0.f, 0.f, 0.f, 0.f);
    if (bias) bb = *reinterpret_cast<const float4*>(bias + n0 + tx * 4);

#pragma unroll
    for (int i = 0; i < 4; ++i) {
        float4 o;
        o.x = acc[i][0] + bb.x;
        o.y = acc[i][1] + bb.y;
        o.z = acc[i][2] + bb.z;
        o.w = acc[i][3] + bb.w;
        *reinterpret_cast<float4*>(
            C + (long long)(m0 + ty * 4 + i) * N + n0 + tx * 4) = o;
    }
}

// ---------------------------------------------------------------------------
// GEMM NN: C[., N] = A[M,K] * B[K,N]. lda=K, ldb=N.
// C write goes to C[m*ldc + h*colPerHead + n] (concatenated-heads layout).
// ---------------------------------------------------------------------------
__global__ void __launch_bounds__(256) gemm_nn(
    const float* __restrict__ A, long long aStride,
    const float* __restrict__ B, long long bStride,
    float* __restrict__ C, long long ldc, int colPerHead,
    int M, int N, int K)
{
    const int h = blockIdx.z;
    A += (long long)h * aStride;
    B += (long long)h * bStride;

    __shared__ __align__(16) float As[BK][BM];
    __shared__ __align__(16) float Bs[BK][BN];

    const int tid = threadIdx.x;
    const int tx = tid & 15;
    const int ty = tid >> 4;
    const int m0 = blockIdx.x * BM;
    const int n0 = blockIdx.y * BN;

    const int aRow = tid >> 2;        // 0..63
    const int aCol = (tid & 3) * 4;   // 0,4,8,12
    const int bRow = tid >> 4;        // 0..15
    const int bCol = (tid & 15) * 4;  // 0..60

    float acc[4][4] = {};

    for (int k0 = 0; k0 < K; k0 += BK) {
        const float4 av = *reinterpret_cast<const float4*>(
            A + (long long)(m0 + aRow) * K + k0 + aCol);
        As[aCol + 0][aRow] = av.x; As[aCol + 1][aRow] = av.y;
        As[aCol + 2][aRow] = av.z; As[aCol + 3][aRow] = av.w;
        const float4 bv = *reinterpret_cast<const float4*>(
            B + (long long)(k0 + bRow) * N + n0 + bCol);
        *reinterpret_cast<float4*>(&Bs[bRow][bCol]) = bv;
        __syncthreads();

#pragma unroll
        for (int kk = 0; kk < BK; ++kk) {
            const float4 a = *reinterpret_cast<const float4*>(&As[kk][ty * 4]);
            const float4 b = *reinterpret_cast<const float4*>(&Bs[kk][tx * 4]);
            acc[0][0] += a.x * b.x; acc[0][1] += a.x * b.y; acc[0][2] += a.x * b.z; acc[0][3] += a.x * b.w;
            acc[1][0] += a.y * b.x; acc[1][1] += a.y * b.y; acc[1][2] += a.y * b.z; acc[1][3] += a.y * b.w;
            acc[2][0] += a.z * b.x; acc[2][1] += a.z * b.y; acc[2][2] += a.z * b.z; acc[2][3] += a.z * b.w;
            acc[3][0] += a.w * b.x; acc[3][1] += a.w * b.y; acc[3][2] += a.w * b.z; acc[3][3] += a.w * b.w;
        }
        __syncthreads();
    }

#pragma unroll
    for (int i = 0; i < 4; ++i) {
        float4 o;
        o.x = acc[i][0]; o.y = acc[i][1]; o.z = acc[i][2]; o.w = acc[i][3];
        *reinterpret_cast<float4*>(
            C + (long long)(m0 + ty * 4 + i) * ldc + (long long)h * colPerHead + n0 + tx * 4) = o;
    }
}

// ---------------------------------------------------------------------------
// In-place row softmax. Row length == THREADS*4 (one float4 per thread).
// exp computed exactly once per element.
// ---------------------------------------------------------------------------
template <int THREADS>
__global__ void __launch_bounds__(THREADS) softmax_rows(float* __restrict__ data)
{
    const long long row = blockIdx.x;
    float4* p = reinterpret_cast<float4*>(data + row * (long long)THREADS * 4);
    float4 v = p[threadIdx.x];

    const int warp = threadIdx.x >> 5;
    const int lane = threadIdx.x & 31;
    constexpr int NW = THREADS / 32;
    __shared__ float smax[NW];
    __shared__ float ssum[NW];

    float mx = fmaxf(fmaxf(v.x, v.y), fmaxf(v.z, v.w));
    mx = warpMax(mx);
    if (lane == 0) smax[warp] = mx;
    __syncthreads();
    if (warp == 0) {
        float t = (lane < NW) ? smax[lane] : -3.4e38f;
        t = warpMax(t);
        if (lane == 0) smax[0] = t;
    }
    __syncthreads();
    mx = smax[0];

    float4 e;
    e.x = __expf(v.x - mx);
    e.y = __expf(v.y - mx);
    e.z = __expf(v.z - mx);
    e.w = __expf(v.w - mx);

    float s = e.x + e.y + e.z + e.w;
    s = warpSum(s);
    if (lane == 0) ssum[warp] = s;
    __syncthreads();
    if (warp == 0) {
        float t = (lane < NW) ? ssum[lane] : 0.f;
        t = warpSum(t);
        if (lane == 0) ssum[0] = t;
    }
    __syncthreads();
    const float inv = 1.0f / ssum[0];

    e.x *= inv; e.y *= inv; e.z *= inv; e.w *= inv;
    p[threadIdx.x] = e;
}

// ---------------------------------------------------------------------------
// Launch
// ---------------------------------------------------------------------------
extern "C" void kernel_launch(void* const* d_in, const int* in_sizes, int n_in,
                              void* d_out, int out_size)
{
    const float* k_in = (const float*)d_in[0];   // [N, O]
    const float* mems = (const float*)d_in[1];   // [H, M, D]
    const float* Wk   = (const float*)d_in[2];   // [H, O, D]
    const float* bk   = (const float*)d_in[3];   // [H, O]
    const float* Wv   = (const float*)d_in[4];   // [H, O, D]
    const float* bv   = (const float*)d_in[5];   // [H, O]
    const float* Wf   = (const float*)d_in[6];   // [O, H*O]
    const float* bf   = (const float*)d_in[7];   // [O]
    float* out = (float*)d_out;                  // [N, O]

    float *memkey, *memval, *att, *X;
    cudaGetSymbolAddress((void**)&memkey, g_memkey);
    cudaGetSymbolAddress((void**)&memval, g_memval);
    cudaGetSymbolAddress((void**)&att,    g_att);
    cudaGetSymbolAddress((void**)&X,      g_X);

    const long long MD = (long long)M_ * D_;    // mems head stride
    const long long OD = (long long)O_ * D_;    // W head stride
    const long long MO = (long long)M_ * O_;    // memkey/memval head stride
    const long long NM = (long long)N_ * M_;    // att head stride

    // 1) key logits
    {
        dim3 grid(M_ / BM, O_ / BN, H_);
        gemm_nt<<<grid, 256>>>(mems, MD, Wk, OD, memkey, MO, bk, O_, M_, O_, D_);
    }
    // 2) mem_val
    {
        dim3 grid(M_ / BM, O_ / BN, H_);
        gemm_nt<<<grid, 256>>>(mems, MD, Wv, OD, memval, MO, bv, O_, M_, O_, D_);
    }
    // 3) softmax over O (row len 512)
    softmax_rows<128><<<H_ * M_, 128>>>(memkey);

    // 4) att = k @ mem_key^T
    {
        dim3 grid(N_ / BM, M_ / BN, H_);
        gemm_nt<<<grid, 256>>>(k_in, 0, memkey, MO, att, NM, nullptr, 0, N_, M_, O_);
    }
    // 5) softmax over M (row len 1024)
    softmax_rows<256><<<H_ * N_, 256>>>(att);

    // 6) out_h = att_w @ mem_val -> X[n, h*O + o]
    {
        dim3 grid(N_ / BM, O_ / BN, H_);
        gemm_nn<<<grid, 256>>>(att, NM, memval, MO, X, (long long)(H_ * O_), O_,
                               N_, O_, M_);
    }
    // 7) out = X @ Wf^T + bf
    {
        dim3 grid(N_ / BM, O_ / BN, 1);
        gemm_nt<<<grid, 256>>>(X, 0, Wf, 0, out, 0, bf, 0, N_, O_, (long long)H_ * O_ == 0 ? 0 : H_ * O_);
    }
}

// round 2
// speedup vs baseline: 2.4210x; 2.4210x over previous
#include <cuda_runtime.h>
#include <cstdint>
#include <cstddef>

// ---------------------------------------------------------------------------
// MultiHeadMemory: H=16, M=1024, D=512, O=512, N=16384
//
//  1. key_logits[h] = mems[h] @ Wk[h]^T + bk[h]   (SIMT NT, fp32)  -> g_memkey
//  2. mem_val[h]    = mems[h] @ Wv[h]^T + bv[h]   (SIMT NT, fp32)  -> g_memval
//  3. softmax rows of g_memkey (len 512), in place
//  3b. transpose mem_val -> g_memvalT [h][O][M]
//  4. att[h] = k @ mem_key[h]^T                   (TF32 MMA NT)    -> g_att
//  5. softmax rows of g_att (len 1024), in place
//  6. X[:, h*O:] = att_w[h] @ memvalT[h]^T        (TF32 MMA NT)    -> g_X
//  7. out = X @ Wf^T + bf                         (TF32 MMA NT)    -> d_out
// ---------------------------------------------------------------------------

#define H_  16
#define M_  1024
#define D_  512
#define O_  512
#define N_  16384

// Scratch (static device globals; allocation-free kernel_launch)
__device__ float g_memkey[(size_t)H_ * M_ * O_];            // 32 MB
__device__ float g_memval[(size_t)H_ * M_ * O_];            // 32 MB
__device__ float g_memvalT[(size_t)H_ * M_ * O_];           // 32 MB
__device__ float g_att[(size_t)H_ * N_ * M_];               // 1 GiB
__device__ float g_X[(size_t)N_ * (H_ * O_)];               // 512 MB

// ---------------------------------------------------------------------------
// Warp reductions
// ---------------------------------------------------------------------------
__device__ __forceinline__ float warpMax(float v) {
#pragma unroll
    for (int o = 16; o > 0; o >>= 1) v = fmaxf(v, __shfl_xor_sync(0xffffffffu, v, o));
    return v;
}
__device__ __forceinline__ float warpSum(float v) {
#pragma unroll
    for (int o = 16; o > 0; o >>= 1) v += __shfl_xor_sync(0xffffffffu, v, o);
    return v;
}

// ---------------------------------------------------------------------------
// SIMT fp32 GEMM NT (used only for the small projection GEMMs, stages 1-2)
// C[M,N] = A[M,K] * B[N,K]^T + bias. 64x64 tile, 256 threads, 4x4 micro-tile.
// ---------------------------------------------------------------------------
#define SBM 64
#define SBN 64
#define SBK 16

__global__ void __launch_bounds__(256) gemm_nt_simt(
    const float* __restrict__ A, long long aStride,
    const float* __restrict__ B, long long bStride,
    float* __restrict__ C, long long cStride,
    const float* __restrict__ bias, long long biasStride,
    int M, int N, int K)
{
    const int h = blockIdx.z;
    A += (long long)h * aStride;
    B += (long long)h * bStride;
    C += (long long)h * cStride;
    if (bias) bias += (long long)h * biasStride;

    __shared__ __align__(16) float As[SBK][SBM];
    __shared__ __align__(16) float Bs[SBK][SBN];

    const int tid = threadIdx.x;
    const int tx = tid & 15;
    const int ty = tid >> 4;
    const int m0 = blockIdx.x * SBM;
    const int n0 = blockIdx.y * SBN;

    const int aRow = tid >> 2;
    const int aCol = (tid & 3) * 4;

    float acc[4][4] = {};

    for (int k0 = 0; k0 < K; k0 += SBK) {
        const float4 av = *reinterpret_cast<const float4*>(
            A + (long long)(m0 + aRow) * K + k0 + aCol);
        const float4 bv = *reinterpret_cast<const float4*>(
            B + (long long)(n0 + aRow) * K + k0 + aCol);
        As[aCol + 0][aRow] = av.x; As[aCol + 1][aRow] = av.y;
        As[aCol + 2][aRow] = av.z; As[aCol + 3][aRow] = av.w;
        Bs[aCol + 0][aRow] = bv.x; Bs[aCol + 1][aRow] = bv.y;
        Bs[aCol + 2][aRow] = bv.z; Bs[aCol + 3][aRow] = bv.w;
        __syncthreads();

#pragma unroll
        for (int kk = 0; kk < SBK; ++kk) {
            const float4 a = *reinterpret_cast<const float4*>(&As[kk][ty * 4]);
            const float4 b = *reinterpret_cast<const float4*>(&Bs[kk][tx * 4]);
            acc[0][0] += a.x * b.x; acc[0][1] += a.x * b.y; acc[0][2] += a.x * b.z; acc[0][3] += a.x * b.w;
            acc[1][0] += a.y * b.x; acc[1][1] += a.y * b.y; acc[1][2] += a.y * b.z; acc[1][3] += a.y * b.w;
            acc[2][0] += a.z * b.x; acc[2][1] += a.z * b.y; acc[2][2] += a.z * b.z; acc[2][3] += a.z * b.w;
            acc[3][0] += a.w * b.x; acc[3][1] += a.w * b.y; acc[3][2] += a.w * b.z; acc[3][3] += a.w * b.w;
        }
        __syncthreads();
    }

    float4 bb = make_float4(0.f, 0.f, 0.f, 0.f);
    if (bias) bb = *reinterpret_cast<const float4*>(bias + n0 + tx * 4);

#pragma unroll
    for (int i = 0; i < 4; ++i) {
        float4 o;
        o.x = acc[i][0] + bb.x;
        o.y = acc[i][1] + bb.y;
        o.z = acc[i][2] + bb.z;
        o.w = acc[i][3] + bb.w;
        *reinterpret_cast<float4*>(
            C + (long long)(m0 + ty * 4 + i) * N + n0 + tx * 4) = o;
    }
}

// ---------------------------------------------------------------------------
// TF32 tensor-core GEMM NT:
//   C[M,N] = A[M,K] * B[N,K]^T (+ bias[N] if non-null)
// 128x128x16 CTA tile, 128 threads (4 warps, 2x2), 64x64 warp tile.
// mma.sync.aligned.m16n8k8.row.col.f32.tf32.tf32.f32.
// cp.async double-buffered SMEM; row pad 20 floats (conflict-free frag LDS).
// All of M,N multiples of 128 and K multiple of 16 in every use here.
// ---------------------------------------------------------------------------
#define TBM 128
#define TBN 128
#define TBK 16
#define TPAD 20   // floats per SMEM row (16 data + 4 pad); 80B, 16B-aligned

__device__ __forceinline__ uint32_t f2tf32(float x) {
    uint32_t r;
    asm("cvt.rna.tf32.f32 %0, %1;" : "=r"(r) : "f"(x));
    return r;
}

__device__ __forceinline__ void cp_async16(uint32_t smem_addr, const float* gptr) {
    asm volatile("cp.async.cg.shared.global [%0], [%1], 16;\n"
                 :: "r"(smem_addr), "l"(gptr));
}

__global__ void __launch_bounds__(128, 2) gemm_nt_tf32(
    const float* __restrict__ A, long long aStride,   // [M,K] row-major
    const float* __restrict__ B, long long bStride,   // [N,K] row-major
    float* __restrict__ C, long long cStride, int ldc,
    const float* __restrict__ bias,                   // [N] or null
    int M, int N, int K)
{
    const int h = blockIdx.z;
    A += (long long)h * aStride;
    B += (long long)h * bStride;
    C += (long long)h * cStride;

    __shared__ __align__(16) float As[2][TBM][TPAD];
    __shared__ __align__(16) float Bs[2][TBN][TPAD];

    const int tid  = threadIdx.x;
    const int lane = tid & 31;
    const int warp = tid >> 5;
    const int g  = lane >> 2;   // groupID        0..7
    const int tg = lane & 3;    // thread in grp  0..3

    const int wm0 = (warp >> 1) * 64;   // warp m offset in CTA tile
    const int wn0 = (warp & 1) * 64;    // warp n offset in CTA tile

    const long long m0 = (long long)blockIdx.y * TBM;
    const long long n0 = (long long)blockIdx.x * TBN;

    // Producer: thread t loads row t of A tile and row t of B tile (4 float4 each).
    const float* aRowPtr = A + (m0 + tid) * K;
    const float* bRowPtr = B + (n0 + tid) * K;

    uint32_t asBase = (uint32_t)__cvta_generic_to_shared(&As[0][0][0]);
    uint32_t bsBase = (uint32_t)__cvta_generic_to_shared(&Bs[0][0][0]);
    const uint32_t bufBytes = TBM * TPAD * 4;   // one buffer
    const uint32_t rowOff   = tid * TPAD * 4;

    float acc[4][8][4];
#pragma unroll
    for (int i = 0; i < 4; ++i)
#pragma unroll
        for (int j = 0; j < 8; ++j)
#pragma unroll
            for (int r = 0; r < 4; ++r) acc[i][j][r] = 0.f;

    const int nIter = K / TBK;

    // prefetch tile 0 into buffer 0
    {
#pragma unroll
        for (int c = 0; c < 4; ++c) {
            cp_async16(asBase + rowOff + c * 16, aRowPtr + c * 4);
            cp_async16(bsBase + rowOff + c * 16, bRowPtr + c * 4);
        }
        asm volatile("cp.async.commit_group;\n" ::);
    }

    for (int kt = 0; kt < nIter; ++kt) {
        asm volatile("cp.async.wait_group 0;\n" ::);
        __syncthreads();

        if (kt + 1 < nIter) {
            const int nb = (kt + 1) & 1;
            const float* ap = aRowPtr + (long long)(kt + 1) * TBK;
            const float* bp = bRowPtr + (long long)(kt + 1) * TBK;
#pragma unroll
            for (int c = 0; c < 4; ++c) {
                cp_async16(asBase + nb * bufBytes + rowOff + c * 16, ap + c * 4);
                cp_async16(bsBase + nb * bufBytes + rowOff + c * 16, bp + c * 4);
            }
            asm volatile("cp.async.commit_group;\n" ::);
        }

        const int buf = kt & 1;
#pragma unroll
        for (int ks = 0; ks < 2; ++ks) {
            // A fragments: 4 m16 tiles
            uint32_t af[4][4];
#pragma unroll
            for (int i = 0; i < 4; ++i) {
                const int r = wm0 + i * 16 + g;
                const int c = ks * 8 + tg;
                af[i][0] = f2tf32(As[buf][r    ][c    ]);
                af[i][1] = f2tf32(As[buf][r + 8][c    ]);
                af[i][2] = f2tf32(As[buf][r    ][c + 4]);
                af[i][3] = f2tf32(As[buf][r + 8][c + 4]);
            }
            // B fragments: 8 n8 tiles
            uint32_t bfr[8][2];
#pragma unroll
            for (int j = 0; j < 8; ++j) {
                const int n = wn0 + j * 8 + g;
                const int c = ks * 8 + tg;
                bfr[j][0] = f2tf32(Bs[buf][n][c    ]);
                bfr[j][1] = f2tf32(Bs[buf][n][c + 4]);
            }
#pragma unroll
            for (int i = 0; i < 4; ++i) {
#pragma unroll
                for (int j = 0; j < 8; ++j) {
                    asm volatile(
                        "mma.sync.aligned.m16n8k8.row.col.f32.tf32.tf32.f32 "
                        "{%0,%1,%2,%3}, {%4,%5,%6,%7}, {%8,%9}, {%0,%1,%2,%3};"
                        : "+f"(acc[i][j][0]), "+f"(acc[i][j][1]),
                          "+f"(acc[i][j][2]), "+f"(acc[i][j][3])
                        : "r"(af[i][0]), "r"(af[i][1]), "r"(af[i][2]), "r"(af[i][3]),
                          "r"(bfr[j][0]), "r"(bfr[j][1]));
                }
            }
        }
        __syncthreads();
    }

    // Epilogue: c0:(g, 2tg) c1:(g, 2tg+1) c2:(g+8, 2tg) c3:(g+8, 2tg+1)
#pragma unroll
    for (int i = 0; i < 4; ++i) {
        const long long r0 = m0 + wm0 + i * 16 + g;
#pragma unroll
        for (int j = 0; j < 8; ++j) {
            const long long cc = n0 + wn0 + j * 8 + 2 * tg;
            float b0 = 0.f, b1 = 0.f;
            if (bias) { b0 = bias[cc]; b1 = bias[cc + 1]; }
            float2 v0 = make_float2(acc[i][j][0] + b0, acc[i][j][1] + b1);
            float2 v1 = make_float2(acc[i][j][2] + b0, acc[i][j][3] + b1);
            *reinterpret_cast<float2*>(C + r0 * ldc + cc) = v0;
            *reinterpret_cast<float2*>(C + (r0 + 8) * ldc + cc) = v1;
        }
    }
}

// ---------------------------------------------------------------------------
// Per-head transpose: in [M_, O_] -> out [O_, M_]   (32x32 tiles, 32x8 block)
// ---------------------------------------------------------------------------
__global__ void __launch_bounds__(256) transpose_mo(
    const float* __restrict__ in, float* __restrict__ out)
{
    __shared__ float t[32][33];
    const int h = blockIdx.z;
    in  += (size_t)h * M_ * O_;
    out += (size_t)h * M_ * O_;

    const int o = blockIdx.x * 32 + threadIdx.x;
    const int m = blockIdx.y * 32 + threadIdx.y;
#pragma unroll
    for (int k = 0; k < 4; ++k)
        t[threadIdx.y + 8 * k][threadIdx.x] = in[(size_t)(m + 8 * k) * O_ + o];
    __syncthreads();

    const int m2 = blockIdx.y * 32 + threadIdx.x;
    const int o2 = blockIdx.x * 32 + threadIdx.y;
#pragma unroll
    for (int k = 0; k < 4; ++k)
        out[(size_t)(o2 + 8 * k) * M_ + m2] = t[threadIdx.x][threadIdx.y + 8 * k];
}

// ---------------------------------------------------------------------------
// In-place row softmax. Row length == THREADS*4.
// ---------------------------------------------------------------------------
template <int THREADS>
__global__ void __launch_bounds__(THREADS) softmax_rows(float* __restrict__ data)
{
    const long long row = blockIdx.x;
    float4* p = reinterpret_cast<float4*>(data + row * (long long)THREADS * 4);
    float4 v = p[threadIdx.x];

    const int warp = threadIdx.x >> 5;
    const int lane = threadIdx.x & 31;
    constexpr int NW = THREADS / 32;
    __shared__ float smax[NW];
    __shared__ float ssum[NW];

    float mx = fmaxf(fmaxf(v.x, v.y), fmaxf(v.z, v.w));
    mx = warpMax(mx);
    if (lane == 0) smax[warp] = mx;
    __syncthreads();
    if (warp == 0) {
        float t = (lane < NW) ? smax[lane] : -3.4e38f;
        t = warpMax(t);
        if (lane == 0) smax[0] = t;
    }
    __syncthreads();
    mx = smax[0];

    float4 e;
    e.x = __expf(v.x - mx);
    e.y = __expf(v.y - mx);
    e.z = __expf(v.z - mx);
    e.w = __expf(v.w - mx);

    float s = e.x + e.y + e.z + e.w;
    s = warpSum(s);
    if (lane == 0) ssum[warp] = s;
    __syncthreads();
    if (warp == 0) {
        float t = (lane < NW) ? ssum[lane] : 0.f;
        t = warpSum(t);
        if (lane == 0) ssum[0] = t;
    }
    __syncthreads();
    const float inv = 1.0f / ssum[0];

    e.x *= inv; e.y *= inv; e.z *= inv; e.w *= inv;
    p[threadIdx.x] = e;
}

// ---------------------------------------------------------------------------
// Launch
// ---------------------------------------------------------------------------
extern "C" void kernel_launch(void* const* d_in, const int* in_sizes, int n_in,
                              void* d_out, int out_size)
{
    const float* k_in = (const float*)d_in[0];   // [N, O]
    const float* mems = (const float*)d_in[1];   // [H, M, D]
    const float* Wk   = (const float*)d_in[2];   // [H, O, D]
    const float* bk   = (const float*)d_in[3];   // [H, O]
    const float* Wv   = (const float*)d_in[4];   // [H, O, D]
    const float* bv   = (const float*)d_in[5];   // [H, O]
    const float* Wf   = (const float*)d_in[6];   // [O, H*O]
    const float* bf   = (const float*)d_in[7];   // [O]
    float* out = (float*)d_out;                  // [N, O]

    float *memkey, *memval, *memvalT, *att, *X;
    cudaGetSymbolAddress((void**)&memkey,  g_memkey);
    cudaGetSymbolAddress((void**)&memval,  g_memval);
    cudaGetSymbolAddress((void**)&memvalT, g_memvalT);
    cudaGetSymbolAddress((void**)&att,     g_att);
    cudaGetSymbolAddress((void**)&X,       g_X);

    const long long MD = (long long)M_ * D_;
    const long long OD = (long long)O_ * D_;
    const long long MO = (long long)M_ * O_;
    const long long NM = (long long)N_ * M_;

    // 1) key logits (fp32 SIMT)
    {
        dim3 grid(M_ / SBM, O_ / SBN, H_);
        gemm_nt_simt<<<grid, 256>>>(mems, MD, Wk, OD, memkey, MO, bk, O_, M_, O_, D_);
    }
    // 2) mem_val (fp32 SIMT)
    {
        dim3 grid(M_ / SBM, O_ / SBN, H_);
        gemm_nt_simt<<<grid, 256>>>(mems, MD, Wv, OD, memval, MO, bv, O_, M_, O_, D_);
    }
    // 3) softmax over O (row len 512)
    softmax_rows<128><<<H_ * M_, 128>>>(memkey);

    // 3b) transpose mem_val per head: [M,O] -> [O,M]
    {
        dim3 grid(O_ / 32, M_ / 32, H_);
        transpose_mo<<<grid, dim3(32, 8)>>>(memval, memvalT);
    }

    // 4) att = k @ mem_key^T   (TF32)  M=N_, N=M_, K=O_
    {
        dim3 grid(M_ / TBN, N_ / TBM, H_);
        gemm_nt_tf32<<<grid, 128>>>(k_in, 0, memkey, MO, att, NM, M_,
                                    nullptr, N_, M_, O_);
    }
    // 5) softmax over M (row len 1024)
    softmax_rows<256><<<H_ * N_, 256>>>(att);

    // 6) X[:, h*O:(h+1)*O] = att_w[h] @ memvalT[h]^T  (TF32)  M=N_, N=O_, K=M_
    {
        dim3 grid(O_ / TBN, N_ / TBM, H_);
        gemm_nt_tf32<<<grid, 128>>>(att, NM, memvalT, MO, X, O_, H_ * O_,
                                    nullptr, N_, O_, M_);
    }
    // 7) out = X @ Wf^T + bf  (TF32)  M=N_, N=O_, K=H_*O_
    {
        dim3 grid(O_ / TBN, N_ / TBM, 1);
        gemm_nt_tf32<<<grid, 128>>>(X, 0, Wf, 0, out, 0, O_,
                                    bf, N_, O_, H_ * O_);
    }
}

// round 3
// speedup vs baseline: 3.2411x; 1.3387x over previous
#include <cuda_runtime.h>
#include <cstdint>
#include <cstddef>

// ---------------------------------------------------------------------------
// MultiHeadMemory: H=16, M=1024, D=512, O=512, N=16384
//
//  0. round external inputs to tf32 (one pass)
//  1. key_logits[h] = rmems[h] @ rWk[h]^T + bk[h]   (TF32)  -> g_memkey
//  2. mem_val[h]    = rmems[h] @ rWv[h]^T + bv[h]   (TF32, round) -> g_memval
//  3. softmax rows of g_memkey (len 512), in place, rounded out
//  3b. GT[h] = Wf_h @ mem_val[h]^T                  (TF32, round) -> g_GT [O,M]
//  4. att[h] = rk @ mem_key[h]^T                    (TF32)  -> g_att
//  5. softmax rows of g_att (len 1024), in place, rounded out
//  6. out = Σ_h att_w[h] @ GT[h]^T + bf             (TF32, K=H*M fused)
// ---------------------------------------------------------------------------

#define H_  16
#define M_  1024
#define D_  512
#define O_  512
#define N_  16384

#define TBM 128
#define TBN 128
#define TBK 16
#define TPAD 20   // floats per SMEM row (16 data + 4 pad)

// Scratch (static device globals; allocation-free kernel_launch)
__device__ float g_memkey[(size_t)H_ * M_ * O_];     // 32 MB
__device__ float g_memval[(size_t)H_ * M_ * O_];     // 32 MB
__device__ float g_GT[(size_t)H_ * M_ * O_];         // 32 MB  [h][O][M]
__device__ float g_att[(size_t)H_ * N_ * M_];        // 1 GiB
__device__ float g_rk[(size_t)N_ * O_];              // 32 MB
__device__ float g_rmems[(size_t)H_ * M_ * D_];      // 32 MB
__device__ float g_rWk[(size_t)H_ * O_ * D_];        // 16 MB
__device__ float g_rWv[(size_t)H_ * O_ * D_];        // 16 MB
__device__ float g_rWf[(size_t)O_ * H_ * O_];        // 16 MB

// ---------------------------------------------------------------------------
__device__ __forceinline__ float rndtf32(float x) {
    uint32_t u;
    asm("cvt.rna.tf32.f32 %0, %1;" : "=r"(u) : "f"(x));
    return __uint_as_float(u);
}

__device__ __forceinline__ float warpMax(float v) {
#pragma unroll
    for (int o = 16; o > 0; o >>= 1) v = fmaxf(v, __shfl_xor_sync(0xffffffffu, v, o));
    return v;
}
__device__ __forceinline__ float warpSum(float v) {
#pragma unroll
    for (int o = 16; o > 0; o >>= 1) v += __shfl_xor_sync(0xffffffffu, v, o);
    return v;
}

__device__ __forceinline__ void cp_async16(uint32_t smem_addr, const float* gptr) {
    asm volatile("cp.async.cg.shared.global [%0], [%1], 16;\n"
                 :: "r"(smem_addr), "l"(gptr));
}

// ---------------------------------------------------------------------------
// Round-to-tf32 copy (vectorized)
// ---------------------------------------------------------------------------
__global__ void __launch_bounds__(256) round_copy(
    const float4* __restrict__ in, float4* __restrict__ out, int n4)
{
    int i = blockIdx.x * 256 + threadIdx.x;
    if (i < n4) {
        float4 v = in[i];
        v.x = rndtf32(v.x); v.y = rndtf32(v.y);
        v.z = rndtf32(v.z); v.w = rndtf32(v.w);
        out[i] = v;
    }
}

// ---------------------------------------------------------------------------
// TF32 tensor-core GEMM NT with pre-rounded inputs (raw-bit feed, no cvt):
//   C[m, n] (+= bias) = sum_k A[m, k] * B[n, k]
// A row ptr: A + z*aHead + m*lda + k      (kSplit == 0)
//            A + (k/kSplit)*aHead + m*lda + (k%kSplit)   (kSplit > 0, z==0)
// 128x128x16 CTA tile, 128 threads (4 warps 2x2), 64x64 warp tile,
// double-buffered cp.async.
// ---------------------------------------------------------------------------
__global__ void __launch_bounds__(128, 2) gemm_nt_tf32(
    const float* __restrict__ A, long long aHead, int lda,
    const float* __restrict__ B, long long bHead, int ldb,
    float* __restrict__ C, long long cHead, int ldc,
    const float* __restrict__ bias, long long biasHead,
    int K, int kSplit, int roundOut)
{
    const int z = blockIdx.z;
    if (kSplit == 0) {
        A += (long long)z * aHead;
        B += (long long)z * bHead;
    }
    C += (long long)z * cHead;
    if (bias) bias += (long long)z * biasHead;

    __shared__ __align__(16) float As[2][TBM][TPAD];
    __shared__ __align__(16) float Bs[2][TBN][TPAD];

    const int tid  = threadIdx.x;
    const int lane = tid & 31;
    const int warp = tid >> 5;
    const int g  = lane >> 2;
    const int tg = lane & 3;

    const int wm0 = (warp >> 1) * 64;
    const int wn0 = (warp & 1) * 64;

    const long long m0 = (long long)blockIdx.y * TBM;
    const long long n0 = (long long)blockIdx.x * TBN;

    uint32_t asBase = (uint32_t)__cvta_generic_to_shared(&As[0][0][0]);
    uint32_t bsBase = (uint32_t)__cvta_generic_to_shared(&Bs[0][0][0]);
    const uint32_t bufBytes = TBM * TPAD * 4;
    const uint32_t rowOff   = tid * TPAD * 4;

    // Precomputed row bases for the contiguous-K case
    const float* aRowPtr = A + (m0 + tid) * (long long)lda;
    const float* bRowPtr = B + (n0 + tid) * (long long)ldb;

    auto loadTile = [&](int kt, int buf) {
        const long long k0 = (long long)kt * TBK;
        const float *ap, *bp;
        if (kSplit > 0) {
            const int kh = (int)(k0 / kSplit);
            const int ko = (int)(k0 - (long long)kh * kSplit);
            ap = aRowPtr + (long long)kh * aHead + ko;
            bp = bRowPtr + (long long)kh * bHead + ko;
        } else {
            ap = aRowPtr + k0;
            bp = bRowPtr + k0;
        }
        const uint32_t ab = asBase + buf * bufBytes + rowOff;
        const uint32_t bb = bsBase + buf * bufBytes + rowOff;
#pragma unroll
        for (int c = 0; c < 4; ++c) {
            cp_async16(ab + c * 16, ap + c * 4);
            cp_async16(bb + c * 16, bp + c * 4);
        }
        asm volatile("cp.async.commit_group;\n" ::);
    };

    float acc[4][8][4];
#pragma unroll
    for (int i = 0; i < 4; ++i)
#pragma unroll
        for (int j = 0; j < 8; ++j)
#pragma unroll
            for (int r = 0; r < 4; ++r) acc[i][j][r] = 0.f;

    const int nIter = K / TBK;

    loadTile(0, 0);

    for (int kt = 0; kt < nIter; ++kt) {
        asm volatile("cp.async.wait_group 0;\n" ::);
        __syncthreads();

        if (kt + 1 < nIter) loadTile(kt + 1, (kt + 1) & 1);

        const int buf = kt & 1;
#pragma unroll
        for (int ks = 0; ks < 2; ++ks) {
            uint32_t af[4][4];
#pragma unroll
            for (int i = 0; i < 4; ++i) {
                const int r = wm0 + i * 16 + g;
                const int c = ks * 8 + tg;
                af[i][0] = __float_as_uint(As[buf][r    ][c    ]);
                af[i][1] = __float_as_uint(As[buf][r + 8][c    ]);
                af[i][2] = __float_as_uint(As[buf][r    ][c + 4]);
                af[i][3] = __float_as_uint(As[buf][r + 8][c + 4]);
            }
            uint32_t bfr[8][2];
#pragma unroll
            for (int j = 0; j < 8; ++j) {
                const int n = wn0 + j * 8 + g;
                const int c = ks * 8 + tg;
                bfr[j][0] = __float_as_uint(Bs[buf][n][c    ]);
                bfr[j][1] = __float_as_uint(Bs[buf][n][c + 4]);
            }
#pragma unroll
            for (int i = 0; i < 4; ++i) {
#pragma unroll
                for (int j = 0; j < 8; ++j) {
                    asm volatile(
                        "mma.sync.aligned.m16n8k8.row.col.f32.tf32.tf32.f32 "
                        "{%0,%1,%2,%3}, {%4,%5,%6,%7}, {%8,%9}, {%0,%1,%2,%3};"
                        : "+f"(acc[i][j][0]), "+f"(acc[i][j][1]),
                          "+f"(acc[i][j][2]), "+f"(acc[i][j][3])
                        : "r"(af[i][0]), "r"(af[i][1]), "r"(af[i][2]), "r"(af[i][3]),
                          "r"(bfr[j][0]), "r"(bfr[j][1]));
                }
            }
        }
        __syncthreads();
    }

    // Epilogue: c0:(g,2tg) c1:(g,2tg+1) c2:(g+8,2tg) c3:(g+8,2tg+1)
#pragma unroll
    for (int i = 0; i < 4; ++i) {
        const long long r0 = m0 + wm0 + i * 16 + g;
#pragma unroll
        for (int j = 0; j < 8; ++j) {
            const long long cc = n0 + wn0 + j * 8 + 2 * tg;
            float b0 = 0.f, b1 = 0.f;
            if (bias) { b0 = bias[cc]; b1 = bias[cc + 1]; }
            float v00 = acc[i][j][0] + b0, v01 = acc[i][j][1] + b1;
            float v10 = acc[i][j][2] + b0, v11 = acc[i][j][3] + b1;
            if (roundOut) {
                v00 = rndtf32(v00); v01 = rndtf32(v01);
                v10 = rndtf32(v10); v11 = rndtf32(v11);
            }
            *reinterpret_cast<float2*>(C + r0 * ldc + cc) = make_float2(v00, v01);
            *reinterpret_cast<float2*>(C + (r0 + 8) * ldc + cc) = make_float2(v10, v11);
        }
    }
}

// ---------------------------------------------------------------------------
// In-place row softmax, output rounded to tf32. Row length == THREADS*4.
// ---------------------------------------------------------------------------
template <int THREADS>
__global__ void __launch_bounds__(THREADS) softmax_rows(float* __restrict__ data)
{
    const long long row = blockIdx.x;
    float4* p = reinterpret_cast<float4*>(data + row * (long long)THREADS * 4);
    float4 v = p[threadIdx.x];

    const int warp = threadIdx.x >> 5;
    const int lane = threadIdx.x & 31;
    constexpr int NW = THREADS / 32;
    __shared__ float smax[NW];
    __shared__ float ssum[NW];

    float mx = fmaxf(fmaxf(v.x, v.y), fmaxf(v.z, v.w));
    mx = warpMax(mx);
    if (lane == 0) smax[warp] = mx;
    __syncthreads();
    if (warp == 0) {
        float t = (lane < NW) ? smax[lane] : -3.4e38f;
        t = warpMax(t);
        if (lane == 0) smax[0] = t;
    }
    __syncthreads();
    mx = smax[0];

    float4 e;
    e.x = __expf(v.x - mx);
    e.y = __expf(v.y - mx);
    e.z = __expf(v.z - mx);
    e.w = __expf(v.w - mx);

    float s = e.x + e.y + e.z + e.w;
    s = warpSum(s);
    if (lane == 0) ssum[warp] = s;
    __syncthreads();
    if (warp == 0) {
        float t = (lane < NW) ? ssum[lane] : 0.f;
        t = warpSum(t);
        if (lane == 0) ssum[0] = t;
    }
    __syncthreads();
    const float inv = 1.0f / ssum[0];

    e.x = rndtf32(e.x * inv);
    e.y = rndtf32(e.y * inv);
    e.z = rndtf32(e.z * inv);
    e.w = rndtf32(e.w * inv);
    p[threadIdx.x] = e;
}

// ---------------------------------------------------------------------------
// Launch
// ---------------------------------------------------------------------------
extern "C" void kernel_launch(void* const* d_in, const int* in_sizes, int n_in,
                              void* d_out, int out_size)
{
    const float* k_in = (const float*)d_in[0];   // [N, O]
    const float* mems = (const float*)d_in[1];   // [H, M, D]
    const float* Wk   = (const float*)d_in[2];   // [H, O, D]
    const float* bk   = (const float*)d_in[3];   // [H, O]
    const float* Wv   = (const float*)d_in[4];   // [H, O, D]
    const float* bv   = (const float*)d_in[5];   // [H, O]
    const float* Wf   = (const float*)d_in[6];   // [O, H*O]
    const float* bf   = (const float*)d_in[7];   // [O]
    float* out = (float*)d_out;                  // [N, O]

    float *memkey, *memval, *GT, *att, *rk, *rmems, *rWk, *rWv, *rWf;
    cudaGetSymbolAddress((void**)&memkey, g_memkey);
    cudaGetSymbolAddress((void**)&memval, g_memval);
    cudaGetSymbolAddress((void**)&GT,     g_GT);
    cudaGetSymbolAddress((void**)&att,    g_att);
    cudaGetSymbolAddress((void**)&rk,     g_rk);
    cudaGetSymbolAddress((void**)&rmems,  g_rmems);
    cudaGetSymbolAddress((void**)&rWk,    g_rWk);
    cudaGetSymbolAddress((void**)&rWv,    g_rWv);
    cudaGetSymbolAddress((void**)&rWf,    g_rWf);

    const long long MD = (long long)M_ * D_;
    const long long OD = (long long)O_ * D_;
    const long long MO = (long long)M_ * O_;
    const long long NM = (long long)N_ * M_;

    // 0) round external inputs to tf32
    {
        auto cp = [&](const float* src, float* dst, long long n) {
            int n4 = (int)(n / 4);
            round_copy<<<(n4 + 255) / 256, 256>>>(
                (const float4*)src, (float4*)dst, n4);
        };
        cp(k_in, rk,   (long long)N_ * O_);
        cp(mems, rmems, (long long)H_ * M_ * D_);
        cp(Wk,  rWk,   (long long)H_ * O_ * D_);
        cp(Wv,  rWv,   (long long)H_ * O_ * D_);
        cp(Wf,  rWf,   (long long)O_ * H_ * O_);
    }

    // 1) key logits: memkey[h][m,o] = rmems[h] @ rWk[h]^T + bk[h]
    {
        dim3 grid(O_ / TBN, M_ / TBM, H_);
        gemm_nt_tf32<<<grid, 128>>>(rmems, MD, D_, rWk, OD, D_,
                                    memkey, MO, O_, bk, O_, D_, 0, 0);
    }
    // 2) mem_val (rounded out; feeds GT gemm)
    {
        dim3 grid(O_ / TBN, M_ / TBM, H_);
        gemm_nt_tf32<<<grid, 128>>>(rmems, MD, D_, rWv, OD, D_,
                                    memval, MO, O_, bv, O_, D_, 0, 1);
    }
    // 3) softmax over O (row len 512), rounded out
    softmax_rows<128><<<H_ * M_, 128>>>(memkey);

    // 3b) GT[h][o,m] = Wf_h @ mem_val[h]^T (rounded out)
    {
        dim3 grid(M_ / TBN, O_ / TBM, H_);
        gemm_nt_tf32<<<grid, 128>>>(rWf, O_, H_ * O_, memval, MO, O_,
                                    GT, MO, M_, nullptr, 0, O_, 0, 1);
    }

    // 4) att = rk @ mem_key^T
    {
        dim3 grid(M_ / TBN, N_ / TBM, H_);
        gemm_nt_tf32<<<grid, 128>>>(rk, 0, O_, memkey, MO, O_,
                                    att, NM, M_, nullptr, 0, O_, 0, 0);
    }
    // 5) softmax over M (row len 1024), rounded out
    softmax_rows<256><<<H_ * N_, 256>>>(att);

    // 6) fused: out[n,o] = Σ_{h,m} att_w[h][n,m] * GT[h][o,m] + bf[o]
    //    K = H*M with kSplit = M (head stride applied per k-tile)
    {
        dim3 grid(O_ / TBN, N_ / TBM, 1);
        gemm_nt_tf32<<<grid, 128>>>(att, NM, M_, GT, MO, M_,
                                    out, 0, O_, bf, 0, H_ * M_, M_, 0);
    }
}

// round 5
// speedup vs baseline: 3.7453x; 1.1556x over previous
#include <cuda_runtime.h>
#include <cstdint>
#include <cstddef>

// ---------------------------------------------------------------------------
// MultiHeadMemory: H=16, M=1024, D=512, O=512, N=16384
// Legacy-path TF32 mma.sync engine (tcgen05 unavailable: harness compiles via
// compute_103 virtual arch; ptxas rejects tcgen05 on sm_103 non-'a' target).
//
//  0. round external inputs to tf32 (one pass)
//  1. key_logits[h] = rmems[h] @ rWk[h]^T + bk[h]      -> g_memkey
//  2. mem_val[h]    = rmems[h] @ rWv[h]^T + bv[h]      -> g_memval (rounded)
//  3. softmax rows of g_memkey (len 512), in place, rounded out
//  3b. GT[h] = Wf_h @ mem_val[h]^T                     -> g_GT [O,M] (rounded)
//  4. att[h] = rk @ mem_key[h]^T                       -> g_att
//  5. softmax rows of g_att (len 1024), in place, rounded out
//  6. out = sum_h att_w[h] @ GT[h]^T + bf              (K = H*M fused)
// ---------------------------------------------------------------------------

#define H_  16
#define M_  1024
#define D_  512
#define O_  512
#define N_  16384

#define TBM 128
#define TBN 128
#define TBK 16
#define TPAD 20   // floats per SMEM row (16 data + 4 pad); 80 B, 16B-aligned

// Scratch (static device globals; allocation-free kernel_launch)
__device__ float g_memkey[(size_t)H_ * M_ * O_];     // 32 MB
__device__ float g_memval[(size_t)H_ * M_ * O_];     // 32 MB
__device__ float g_GT[(size_t)H_ * M_ * O_];         // 32 MB  [h][O][M]
__device__ float g_att[(size_t)H_ * N_ * M_];        // 1 GiB
__device__ float g_rk[(size_t)N_ * O_];              // 32 MB
__device__ float g_rmems[(size_t)H_ * M_ * D_];      // 32 MB
__device__ float g_rWk[(size_t)H_ * O_ * D_];        // 16 MB
__device__ float g_rWv[(size_t)H_ * O_ * D_];        // 16 MB
__device__ float g_rWf[(size_t)O_ * H_ * O_];        // 16 MB

// ---------------------------------------------------------------------------
__device__ __forceinline__ float rndtf32(float x) {
    uint32_t u;
    asm("cvt.rna.tf32.f32 %0, %1;" : "=r"(u) : "f"(x));
    return __uint_as_float(u);
}

__device__ __forceinline__ float warpMax(float v) {
#pragma unroll
    for (int o = 16; o > 0; o >>= 1) v = fmaxf(v, __shfl_xor_sync(0xffffffffu, v, o));
    return v;
}
__device__ __forceinline__ float warpSum(float v) {
#pragma unroll
    for (int o = 16; o > 0; o >>= 1) v += __shfl_xor_sync(0xffffffffu, v, o);
    return v;
}

__device__ __forceinline__ void cp_async16(uint32_t smem_addr, const float* gptr) {
    asm volatile("cp.async.cg.shared.global [%0], [%1], 16;\n"
                 :: "r"(smem_addr), "l"(gptr));
}

// ---------------------------------------------------------------------------
// Round-to-tf32 copy (vectorized)
// ---------------------------------------------------------------------------
__global__ void __launch_bounds__(256) round_copy(
    const float4* __restrict__ in, float4* __restrict__ out, int n4)
{
    int i = blockIdx.x * 256 + threadIdx.x;
    if (i < n4) {
        float4 v = in[i];
        v.x = rndtf32(v.x); v.y = rndtf32(v.y);
        v.z = rndtf32(v.z); v.w = rndtf32(v.w);
        out[i] = v;
    }
}

// ---------------------------------------------------------------------------
// TF32 tensor-core GEMM NT (pre-rounded inputs, raw-bit feed):
//   C[m, n] = sum_k A[m, k] * B[n, k]  (+ bias[n])
// A row ptr: A + z*aHead + m*lda + k             (kSplit == 0)
//            A + (k/kSplit)*aHead + m*lda + k%kSplit   (kSplit > 0, z==0)
// 128x128x16 CTA tile, 256 threads (8 warps, 4x2), 32x64 warp tile,
// double-buffered cp.async.  4 warps/SMSP at 2 CTAs/SM for latency hiding.
// ---------------------------------------------------------------------------
__global__ void __launch_bounds__(256, 2) gemm_nt_tf32(
    const float* __restrict__ A, long long aHead, long long lda,
    const float* __restrict__ B, long long bHead, long long ldb,
    float* __restrict__ C, long long cHead, long long ldc,
    const float* __restrict__ bias, long long biasHead,
    int K, int kSplit, int roundOut)
{
    const int z = blockIdx.z;
    if (kSplit == 0) {
        A += (long long)z * aHead;
        B += (long long)z * bHead;
    }
    C += (long long)z * cHead;
    if (bias) bias += (long long)z * biasHead;

    __shared__ __align__(16) float As[2][TBM][TPAD];
    __shared__ __align__(16) float Bs[2][TBN][TPAD];

    const int tid  = threadIdx.x;
    const int lane = tid & 31;
    const int warp = tid >> 5;
    const int g  = lane >> 2;   // 0..7
    const int tg = lane & 3;    // 0..3

    const int wm0 = (warp & 3) * 32;   // warp m offset (4 warps along M)
    const int wn0 = (warp >> 2) * 64;  // warp n offset (2 warps along N)

    const long long m0 = (long long)blockIdx.y * TBM;
    const long long n0 = (long long)blockIdx.x * TBN;

    uint32_t asBase = (uint32_t)__cvta_generic_to_shared(&As[0][0][0]);
    uint32_t bsBase = (uint32_t)__cvta_generic_to_shared(&Bs[0][0][0]);
    const uint32_t bufBytes = TBM * TPAD * 4;

    // Producer: 256 threads; thread t covers row t>>1, chunks {2(t&1), 2(t&1)+1}.
    const int pRow = tid >> 1;
    const int pCh  = (tid & 1) * 2;
    const uint32_t rowOff = pRow * TPAD * 4 + pCh * 16;

    const float* aRowPtr = A + (m0 + pRow) * lda + pCh * 4;
    const float* bRowPtr = B + (n0 + pRow) * ldb + pCh * 4;

    auto loadTile = [&](int kt, int buf) {
        const long long k0 = (long long)kt * TBK;
        long long kA, kB;
        if (kSplit > 0) {
            const long long kh = k0 / kSplit;
            const long long ko = k0 - kh * kSplit;
            kA = kh * aHead + ko;
            kB = kh * bHead + ko;
        } else {
            kA = k0; kB = k0;
        }
        const uint32_t ab = asBase + buf * bufBytes + rowOff;
        const uint32_t bb = bsBase + buf * bufBytes + rowOff;
#pragma unroll
        for (int c = 0; c < 2; ++c) {
            cp_async16(ab + c * 16, aRowPtr + kA + c * 4);
            cp_async16(bb + c * 16, bRowPtr + kB + c * 4);
        }
        asm volatile("cp.async.commit_group;\n" ::);
    };

    float acc[2][8][4];
#pragma unroll
    for (int i = 0; i < 2; ++i)
#pragma unroll
        for (int j = 0; j < 8; ++j)
#pragma unroll
            for (int r = 0; r < 4; ++r) acc[i][j][r] = 0.f;

    const int nIter = K / TBK;

    loadTile(0, 0);

    for (int kt = 0; kt < nIter; ++kt) {
        asm volatile("cp.async.wait_group 0;\n" ::);
        __syncthreads();

        if (kt + 1 < nIter) loadTile(kt + 1, (kt + 1) & 1);

        const int buf = kt & 1;
#pragma unroll
        for (int ks = 0; ks < 2; ++ks) {
            const int c = ks * 8 + tg;
            uint32_t af[2][4];
#pragma unroll
            for (int i = 0; i < 2; ++i) {
                const int r = wm0 + i * 16 + g;
                af[i][0] = __float_as_uint(As[buf][r    ][c    ]);
                af[i][1] = __float_as_uint(As[buf][r + 8][c    ]);
                af[i][2] = __float_as_uint(As[buf][r    ][c + 4]);
                af[i][3] = __float_as_uint(As[buf][r + 8][c + 4]);
            }
            uint32_t bfr[8][2];
#pragma unroll
            for (int j = 0; j < 8; ++j) {
                const int n = wn0 + j * 8 + g;
                bfr[j][0] = __float_as_uint(Bs[buf][n][c    ]);
                bfr[j][1] = __float_as_uint(Bs[buf][n][c + 4]);
            }
#pragma unroll
            for (int i = 0; i < 2; ++i) {
#pragma unroll
                for (int j = 0; j < 8; ++j) {
                    asm volatile(
                        "mma.sync.aligned.m16n8k8.row.col.f32.tf32.tf32.f32 "
                        "{%0,%1,%2,%3}, {%4,%5,%6,%7}, {%8,%9}, {%0,%1,%2,%3};"
                        : "+f"(acc[i][j][0]), "+f"(acc[i][j][1]),
                          "+f"(acc[i][j][2]), "+f"(acc[i][j][3])
                        : "r"(af[i][0]), "r"(af[i][1]), "r"(af[i][2]), "r"(af[i][3]),
                          "r"(bfr[j][0]), "r"(bfr[j][1]));
                }
            }
        }
        __syncthreads();
    }

    // Epilogue: c0:(g,2tg) c1:(g,2tg+1) c2:(g+8,2tg) c3:(g+8,2tg+1)
#pragma unroll
    for (int i = 0; i < 2; ++i) {
        const long long r0 = m0 + wm0 + i * 16 + g;
#pragma unroll
        for (int j = 0; j < 8; ++j) {
            const long long cc = n0 + wn0 + j * 8 + 2 * tg;
            float b0 = 0.f, b1 = 0.f;
            if (bias) { b0 = bias[cc]; b1 = bias[cc + 1]; }
            float v00 = acc[i][j][0] + b0, v01 = acc[i][j][1] + b1;
            float v10 = acc[i][j][2] + b0, v11 = acc[i][j][3] + b1;
            if (roundOut) {
                v00 = rndtf32(v00); v01 = rndtf32(v01);
                v10 = rndtf32(v10); v11 = rndtf32(v11);
            }
            *reinterpret_cast<float2*>(C + r0 * ldc + cc) = make_float2(v00, v01);
            *reinterpret_cast<float2*>(C + (r0 + 8) * ldc + cc) = make_float2(v10, v11);
        }
    }
}

// ---------------------------------------------------------------------------
// In-place row softmax, output rounded to tf32. Row length == THREADS*4.
// ---------------------------------------------------------------------------
template <int THREADS>
__global__ void __launch_bounds__(THREADS) softmax_rows(float* __restrict__ data)
{
    const long long row = blockIdx.x;
    float4* p = reinterpret_cast<float4*>(data + row * (long long)THREADS * 4);
    float4 v = p[threadIdx.x];

    const int warp = threadIdx.x >> 5;
    const int lane = threadIdx.x & 31;
    constexpr int NW = THREADS / 32;
    __shared__ float smax[NW];
    __shared__ float ssum[NW];

    float mx = fmaxf(fmaxf(v.x, v.y), fmaxf(v.z, v.w));
    mx = warpMax(mx);
    if (lane == 0) smax[warp] = mx;
    __syncthreads();
    if (warp == 0) {
        float t = (lane < NW) ? smax[lane] : -3.4e38f;
        t = warpMax(t);
        if (lane == 0) smax[0] = t;
    }
    __syncthreads();
    mx = smax[0];

    float4 e;
    e.x = __expf(v.x - mx);
    e.y = __expf(v.y - mx);
    e.z = __expf(v.z - mx);
    e.w = __expf(v.w - mx);

    float s = e.x + e.y + e.z + e.w;
    s = warpSum(s);
    if (lane == 0) ssum[warp] = s;
    __syncthreads();
    if (warp == 0) {
        float t = (lane < NW) ? ssum[lane] : 0.f;
        t = warpSum(t);
        if (lane == 0) ssum[0] = t;
    }
    __syncthreads();
    const float inv = 1.0f / ssum[0];

    e.x = rndtf32(e.x * inv);
    e.y = rndtf32(e.y * inv);
    e.z = rndtf32(e.z * inv);
    e.w = rndtf32(e.w * inv);
    p[threadIdx.x] = e;
}

// ---------------------------------------------------------------------------
// Launch
// ---------------------------------------------------------------------------
extern "C" void kernel_launch(void* const* d_in, const int* in_sizes, int n_in,
                              void* d_out, int out_size)
{
    const float* k_in = (const float*)d_in[0];   // [N, O]
    const float* mems = (const float*)d_in[1];   // [H, M, D]
    const float* Wk   = (const float*)d_in[2];   // [H, O, D]
    const float* bk   = (const float*)d_in[3];   // [H, O]
    const float* Wv   = (const float*)d_in[4];   // [H, O, D]
    const float* bv   = (const float*)d_in[5];   // [H, O]
    const float* Wf   = (const float*)d_in[6];   // [O, H*O]
    const float* bf   = (const float*)d_in[7];   // [O]
    float* out = (float*)d_out;                  // [N, O]

    float *memkey, *memval, *GT, *att, *rk, *rmems, *rWk, *rWv, *rWf;
    cudaGetSymbolAddress((void**)&memkey, g_memkey);
    cudaGetSymbolAddress((void**)&memval, g_memval);
    cudaGetSymbolAddress((void**)&GT,     g_GT);
    cudaGetSymbolAddress((void**)&att,    g_att);
    cudaGetSymbolAddress((void**)&rk,     g_rk);
    cudaGetSymbolAddress((void**)&rmems,  g_rmems);
    cudaGetSymbolAddress((void**)&rWk,    g_rWk);
    cudaGetSymbolAddress((void**)&rWv,    g_rWv);
    cudaGetSymbolAddress((void**)&rWf,    g_rWf);

    const long long MD = (long long)M_ * D_;
    const long long OD = (long long)O_ * D_;
    const long long MO = (long long)M_ * O_;
    const long long NM = (long long)N_ * M_;

    // 0) round external inputs to tf32
    {
        auto cp = [&](const float* src, float* dst, long long n) {
            int n4 = (int)(n / 4);
            round_copy<<<(n4 + 255) / 256, 256>>>(
                (const float4*)src, (float4*)dst, n4);
        };
        cp(k_in, rk,    (long long)N_ * O_);
        cp(mems, rmems, (long long)H_ * M_ * D_);
        cp(Wk,  rWk,    (long long)H_ * O_ * D_);
        cp(Wv,  rWv,    (long long)H_ * O_ * D_);
        cp(Wf,  rWf,    (long long)O_ * H_ * O_);
    }

    // 1) key logits: memkey[h][m,o] = rmems[h] @ rWk[h]^T + bk[h]
    {
        dim3 grid(O_ / TBN, M_ / TBM, H_);
        gemm_nt_tf32<<<grid, 256>>>(rmems, MD, D_, rWk, OD, D_,
                                    memkey, MO, O_, bk, O_, D_, 0, 0);
    }
    // 2) mem_val (rounded out; feeds GT gemm)
    {
        dim3 grid(O_ / TBN, M_ / TBM, H_);
        gemm_nt_tf32<<<grid, 256>>>(rmems, MD, D_, rWv, OD, D_,
                                    memval, MO, O_, bv, O_, D_, 0, 1);
    }
    // 3) softmax over O (row len 512), rounded out
    softmax_rows<128><<<H_ * M_, 128>>>(memkey);

    // 3b) GT[h][o,m] = Wf_h @ mem_val[h]^T (rounded out)
    {
        dim3 grid(M_ / TBN, O_ / TBM, H_);
        gemm_nt_tf32<<<grid, 256>>>(rWf, O_, H_ * O_, memval, MO, O_,
                                    GT, MO, M_, nullptr, 0, O_, 0, 1);
    }

    // 4) att = rk @ mem_key^T
    {
        dim3 grid(M_ / TBN, N_ / TBM, H_);
        gemm_nt_tf32<<<grid, 256>>>(rk, 0, O_, memkey, MO, O_,
                                    att, NM, M_, nullptr, 0, O_, 0, 0);
    }
    // 5) softmax over M (row len 1024), rounded out
    softmax_rows<256><<<H_ * N_, 256>>>(att);

    // 6) fused: out[n,o] = sum_{h,m} att_w[h][n,m] * GT[h][o,m] + bf[o]
    {
        dim3 grid(O_ / TBN, N_ / TBM, 1);
        gemm_nt_tf32<<<grid, 256>>>(att, NM, M_, GT, MO, M_,
                                    out, 0, O_, bf, 0, H_ * M_, M_, 0);
    }
}

// round 6
// speedup vs baseline: 7.4077x; 1.9779x over previous
#include <cuda_runtime.h>
#include <cuda_fp16.h>
#include <cstdint>
#include <cstddef>

// ---------------------------------------------------------------------------
// MultiHeadMemory: H=16, M=1024, D=512, O=512, N=16384
// fp16 mma.sync (m16n8k16) engine, fp32 accumulate. fp16 mantissa == tf32
// mantissa (11 bits) -> same numerics as the tf32 build, 2x the rate.
//
//  0. convert inputs fp32 -> fp16 (one pass)
//  1. key_logits[h] = memsh[h] @ Wkh[h]^T + bk[h]  -> g_memkey (fp32)
//  2. mem_val[h]    = memsh[h] @ Wvh[h]^T + bv[h]  -> g_memvalh (fp16)
//  3. softmax rows of g_memkey (len 512)           -> g_memkeyh (fp16)
//  3b. GT[h] = Wf_h @ mem_val[h]^T                 -> g_GTh [O,M] (fp16)
//  4. att[h] = kh @ mem_key[h]^T                   -> g_att (fp32)
//  5. softmax rows of g_att (len 1024)             -> g_atth (fp16)
//  6. out = sum_h att_w[h] @ GT[h]^T + bf          (K = H*M fused, fp32 out)
// ---------------------------------------------------------------------------

#define H_  16
#define M_  1024
#define D_  512
#define O_  512
#define N_  16384

#define TBM 128
#define TBN 128
#define TBK 32          // halves per k-tile
#define ROWB 80         // bytes per SMEM row: 64 B data + 16 B pad

// fp32 scratch
__device__ float g_memkey[(size_t)H_ * M_ * O_];     // 32 MB (logits)
__device__ float g_att[(size_t)H_ * N_ * M_];        // 1 GiB (logits)
// fp16 scratch
__device__ __half g_kh[(size_t)N_ * O_];
__device__ __half g_memsh[(size_t)H_ * M_ * D_];
__device__ __half g_Wkh[(size_t)H_ * O_ * D_];
__device__ __half g_Wvh[(size_t)H_ * O_ * D_];
__device__ __half g_Wfh[(size_t)O_ * H_ * O_];
__device__ __half g_memkeyh[(size_t)H_ * M_ * O_];
__device__ __half g_memvalh[(size_t)H_ * M_ * O_];
__device__ __half g_GTh[(size_t)H_ * M_ * O_];       // [h][O][M]
__device__ __half g_atth[(size_t)H_ * N_ * M_];      // 0.5 GiB

// ---------------------------------------------------------------------------
__device__ __forceinline__ float warpMax(float v) {
#pragma unroll
    for (int o = 16; o > 0; o >>= 1) v = fmaxf(v, __shfl_xor_sync(0xffffffffu, v, o));
    return v;
}
__device__ __forceinline__ float warpSum(float v) {
#pragma unroll
    for (int o = 16; o > 0; o >>= 1) v += __shfl_xor_sync(0xffffffffu, v, o);
    return v;
}
__device__ __forceinline__ void cp_async16(uint32_t smem_addr, const void* gptr) {
    asm volatile("cp.async.cg.shared.global [%0], [%1], 16;\n"
                 :: "r"(smem_addr), "l"(gptr));
}
__device__ __forceinline__ void ldmatrix_x4(uint32_t& r0, uint32_t& r1,
                                            uint32_t& r2, uint32_t& r3,
                                            uint32_t addr) {
    asm volatile("ldmatrix.sync.aligned.m8n8.x4.shared.b16 {%0,%1,%2,%3}, [%4];"
                 : "=r"(r0), "=r"(r1), "=r"(r2), "=r"(r3) : "r"(addr));
}

// ---------------------------------------------------------------------------
// fp32 -> fp16 convert (8 floats / thread)
// ---------------------------------------------------------------------------
__global__ void __launch_bounds__(256) cvt_f32_f16(
    const float4* __restrict__ in, uint2* __restrict__ out, int n8)
{
    int i = blockIdx.x * 256 + threadIdx.x;
    if (i < n8) {
        float4 a = in[2 * i];
        float4 b = in[2 * i + 1];
        __half2 h0 = __floats2half2_rn(a.x, a.y);
        __half2 h1 = __floats2half2_rn(a.z, a.w);
        __half2 h2 = __floats2half2_rn(b.x, b.y);
        __half2 h3 = __floats2half2_rn(b.z, b.w);
        uint2 o0, o1;
        o0.x = *reinterpret_cast<uint32_t*>(&h0);
        o0.y = *reinterpret_cast<uint32_t*>(&h1);
        o1.x = *reinterpret_cast<uint32_t*>(&h2);
        o1.y = *reinterpret_cast<uint32_t*>(&h3);
        out[2 * i] = o0;
        out[2 * i + 1] = o1;
    }
}

// ---------------------------------------------------------------------------
// fp16 tensor-core GEMM NT, fp32 accumulate:
//   C[m, n] = sum_k A[m, k] * B[n, k]  (+ bias[n])
// A row ptr: A + z*aHead + m*lda + k              (kSplit == 0)
//            A + (k/kSplit)*aHead + m*lda + k%kSplit   (kSplit > 0, z==0)
// 128x128x32 CTA tile, 256 threads (8 warps, 4x2 / 32x64 warp tile),
// double-buffered cp.async, ldmatrix.x4 fragment loads.
// ---------------------------------------------------------------------------
__global__ void __launch_bounds__(256, 2) gemm_nt_f16(
    const __half* __restrict__ A, long long aHead, long long lda,
    const __half* __restrict__ B, long long bHead, long long ldb,
    void* __restrict__ Cv, long long cHead, long long ldc,
    const float* __restrict__ bias, long long biasHead,
    int K, int kSplit, int outHalf)
{
    const int z = blockIdx.z;
    if (kSplit == 0) {
        A += (long long)z * aHead;
        B += (long long)z * bHead;
    }
    if (bias) bias += (long long)z * biasHead;

    // SMEM: [buf][A(10240 B) | B(10240 B)]
    __shared__ __align__(16) char smraw[2 * 2 * TBM * ROWB];
    const uint32_t smBase = (uint32_t)__cvta_generic_to_shared(smraw);
    const uint32_t BUFB = 2 * TBM * ROWB;          // 20480
    const uint32_t BOFF = TBM * ROWB;              // 10240 (B tile offset)

    const int tid  = threadIdx.x;
    const int lane = tid & 31;
    const int warp = tid >> 5;
    const int g  = lane >> 2;
    const int tg = lane & 3;

    const int wm0 = (warp & 3) * 32;
    const int wn0 = (warp >> 2) * 64;

    const long long m0 = (long long)blockIdx.y * TBM;
    const long long n0 = (long long)blockIdx.x * TBN;

    // Producer mapping: thread t -> row t>>1, chunks 2(t&1), 2(t&1)+1 (16B each)
    const int pRow = tid >> 1;
    const int pCh  = (tid & 1) * 2;
    const uint32_t prodOff = (uint32_t)(pRow * ROWB + pCh * 16);

    const __half* aRowPtr = A + (m0 + pRow) * lda + pCh * 8;
    const __half* bRowPtr = B + (n0 + pRow) * ldb + pCh * 8;

    auto loadTile = [&](int kt, int buf) {
        const long long k0 = (long long)kt * TBK;
        long long kA, kB;
        if (kSplit > 0) {
            const long long kh = k0 / kSplit;
            const long long ko = k0 - kh * kSplit;
            kA = kh * aHead + ko;
            kB = kh * bHead + ko;
        } else {
            kA = k0; kB = k0;
        }
        const uint32_t ab = smBase + buf * BUFB + prodOff;
        const uint32_t bb = ab + BOFF;
#pragma unroll
        for (int c = 0; c < 2; ++c) {
            cp_async16(ab + c * 16, aRowPtr + kA + c * 8);
            cp_async16(bb + c * 16, bRowPtr + kB + c * 8);
        }
        asm volatile("cp.async.commit_group;\n" ::);
    };

    // ldmatrix per-thread address offsets (within a buffer), bytes.
    // A, mtile i: matrix = lane>>3 -> row = wm0+16i+(mat&1)*8+(lane&7),
    //             chunk = mat>>1 (16 B). Per kstep add s*32.
    const int mat  = lane >> 3;
    const int row8 = lane & 7;
    uint32_t aOff[2], bOff[4];
#pragma unroll
    for (int i = 0; i < 2; ++i)
        aOff[i] = (uint32_t)((wm0 + i * 16 + (mat & 1) * 8 + row8) * ROWB
                             + (mat >> 1) * 16);
#pragma unroll
    for (int p = 0; p < 4; ++p)
        bOff[p] = (uint32_t)(BOFF + (wn0 + (2 * p + (mat >> 1)) * 8 + row8) * ROWB
                             + (mat & 1) * 16);

    float acc[2][8][4];
#pragma unroll
    for (int i = 0; i < 2; ++i)
#pragma unroll
        for (int j = 0; j < 8; ++j)
#pragma unroll
            for (int r = 0; r < 4; ++r) acc[i][j][r] = 0.f;

    const int nIter = K / TBK;
    loadTile(0, 0);

    for (int kt = 0; kt < nIter; ++kt) {
        asm volatile("cp.async.wait_group 0;\n" ::);
        __syncthreads();

        if (kt + 1 < nIter) loadTile(kt + 1, (kt + 1) & 1);

        const uint32_t base = smBase + (uint32_t)(kt & 1) * BUFB;
#pragma unroll
        for (int ks = 0; ks < 2; ++ks) {
            const uint32_t ksb = base + ks * 32;
            uint32_t af[2][4];
#pragma unroll
            for (int i = 0; i < 2; ++i)
                ldmatrix_x4(af[i][0], af[i][1], af[i][2], af[i][3], ksb + aOff[i]);
            uint32_t bf[8][2];
#pragma unroll
            for (int p = 0; p < 4; ++p)
                ldmatrix_x4(bf[2 * p][0], bf[2 * p][1],
                            bf[2 * p + 1][0], bf[2 * p + 1][1], ksb + bOff[p]);
#pragma unroll
            for (int i = 0; i < 2; ++i) {
#pragma unroll
                for (int j = 0; j < 8; ++j) {
                    asm volatile(
                        "mma.sync.aligned.m16n8k16.row.col.f32.f16.f16.f32 "
                        "{%0,%1,%2,%3}, {%4,%5,%6,%7}, {%8,%9}, {%0,%1,%2,%3};"
                        : "+f"(acc[i][j][0]), "+f"(acc[i][j][1]),
                          "+f"(acc[i][j][2]), "+f"(acc[i][j][3])
                        : "r"(af[i][0]), "r"(af[i][1]), "r"(af[i][2]), "r"(af[i][3]),
                          "r"(bf[j][0]), "r"(bf[j][1]));
                }
            }
        }
        __syncthreads();
    }

    // Epilogue: c0:(g,2tg) c1:(g,2tg+1) c2:(g+8,2tg) c3:(g+8,2tg+1)
    const long long cBase = (long long)z * cHead;
#pragma unroll
    for (int i = 0; i < 2; ++i) {
        const long long r0 = m0 + wm0 + i * 16 + g;
#pragma unroll
        for (int j = 0; j < 8; ++j) {
            const long long cc = n0 + wn0 + j * 8 + 2 * tg;
            float b0 = 0.f, b1 = 0.f;
            if (bias) { b0 = bias[cc]; b1 = bias[cc + 1]; }
            float v00 = acc[i][j][0] + b0, v01 = acc[i][j][1] + b1;
            float v10 = acc[i][j][2] + b0, v11 = acc[i][j][3] + b1;
            if (outHalf) {
                __half* C = (__half*)Cv + cBase;
                __half2 h0 = __floats2half2_rn(v00, v01);
                __half2 h1 = __floats2half2_rn(v10, v11);
                *reinterpret_cast<__half2*>(C + r0 * ldc + cc) = h0;
                *reinterpret_cast<__half2*>(C + (r0 + 8) * ldc + cc) = h1;
            } else {
                float* C = (float*)Cv + cBase;
                *reinterpret_cast<float2*>(C + r0 * ldc + cc) = make_float2(v00, v01);
                *reinterpret_cast<float2*>(C + (r0 + 8) * ldc + cc) = make_float2(v10, v11);
            }
        }
    }
}

// ---------------------------------------------------------------------------
// Row softmax fp32 -> fp16. Row length == THREADS*4.
// ---------------------------------------------------------------------------
template <int THREADS>
__global__ void __launch_bounds__(THREADS) softmax_rows_h(
    const float* __restrict__ in, __half* __restrict__ out)
{
    const long long row = blockIdx.x;
    const float4* p = reinterpret_cast<const float4*>(in + row * (long long)THREADS * 4);
    float4 v = p[threadIdx.x];

    const int warp = threadIdx.x >> 5;
    const int lane = threadIdx.x & 31;
    constexpr int NW = THREADS / 32;
    __shared__ float smax[NW];
    __shared__ float ssum[NW];

    float mx = fmaxf(fmaxf(v.x, v.y), fmaxf(v.z, v.w));
    mx = warpMax(mx);
    if (lane == 0) smax[warp] = mx;
    __syncthreads();
    if (warp == 0) {
        float t = (lane < NW) ? smax[lane] : -3.4e38f;
        t = warpMax(t);
        if (lane == 0) smax[0] = t;
    }
    __syncthreads();
    mx = smax[0];

    float4 e;
    e.x = __expf(v.x - mx);
    e.y = __expf(v.y - mx);
    e.z = __expf(v.z - mx);
    e.w = __expf(v.w - mx);

    float s = e.x + e.y + e.z + e.w;
    s = warpSum(s);
    if (lane == 0) ssum[warp] = s;
    __syncthreads();
    if (warp == 0) {
        float t = (lane < NW) ? ssum[lane] : 0.f;
        t = warpSum(t);
        if (lane == 0) ssum[0] = t;
    }
    __syncthreads();
    const float inv = 1.0f / ssum[0];

    __half2 h0 = __floats2half2_rn(e.x * inv, e.y * inv);
    __half2 h1 = __floats2half2_rn(e.z * inv, e.w * inv);
    uint2 o;
    o.x = *reinterpret_cast<uint32_t*>(&h0);
    o.y = *reinterpret_cast<uint32_t*>(&h1);
    *reinterpret_cast<uint2*>(out + row * (long long)THREADS * 4 + threadIdx.x * 4) = o;
}

// ---------------------------------------------------------------------------
// Launch
// ---------------------------------------------------------------------------
extern "C" void kernel_launch(void* const* d_in, const int* in_sizes, int n_in,
                              void* d_out, int out_size)
{
    const float* k_in = (const float*)d_in[0];   // [N, O]
    const float* mems = (const float*)d_in[1];   // [H, M, D]
    const float* Wk   = (const float*)d_in[2];   // [H, O, D]
    const float* bk   = (const float*)d_in[3];   // [H, O]
    const float* Wv   = (const float*)d_in[4];   // [H, O, D]
    const float* bv   = (const float*)d_in[5];   // [H, O]
    const float* Wf   = (const float*)d_in[6];   // [O, H*O]
    const float* bf   = (const float*)d_in[7];   // [O]
    float* out = (float*)d_out;                  // [N, O]

    float *memkey, *att;
    __half *kh, *memsh, *Wkh, *Wvh, *Wfh, *memkeyh, *memvalh, *GTh, *atth;
    cudaGetSymbolAddress((void**)&memkey,  g_memkey);
    cudaGetSymbolAddress((void**)&att,     g_att);
    cudaGetSymbolAddress((void**)&kh,      g_kh);
    cudaGetSymbolAddress((void**)&memsh,   g_memsh);
    cudaGetSymbolAddress((void**)&Wkh,     g_Wkh);
    cudaGetSymbolAddress((void**)&Wvh,     g_Wvh);
    cudaGetSymbolAddress((void**)&Wfh,     g_Wfh);
    cudaGetSymbolAddress((void**)&memkeyh, g_memkeyh);
    cudaGetSymbolAddress((void**)&memvalh, g_memvalh);
    cudaGetSymbolAddress((void**)&GTh,     g_GTh);
    cudaGetSymbolAddress((void**)&atth,    g_atth);

    const long long MD = (long long)M_ * D_;
    const long long OD = (long long)O_ * D_;
    const long long MO = (long long)M_ * O_;
    const long long NM = (long long)N_ * M_;

    // 0) convert inputs to fp16
    {
        auto cv = [&](const float* src, __half* dst, long long n) {
            int n8 = (int)(n / 8);
            cvt_f32_f16<<<(n8 + 255) / 256, 256>>>(
                (const float4*)src, (uint2*)dst, n8);
        };
        cv(k_in, kh,    (long long)N_ * O_);
        cv(mems, memsh, (long long)H_ * M_ * D_);
        cv(Wk,  Wkh,    (long long)H_ * O_ * D_);
        cv(Wv,  Wvh,    (long long)H_ * O_ * D_);
        cv(Wf,  Wfh,    (long long)O_ * H_ * O_);
    }

    // 1) key logits (fp32 out): memkey[h][m,o] = memsh[h] @ Wkh[h]^T + bk[h]
    {
        dim3 grid(O_ / TBN, M_ / TBM, H_);
        gemm_nt_f16<<<grid, 256>>>(memsh, MD, D_, Wkh, OD, D_,
                                   memkey, MO, O_, bk, O_, D_, 0, 0);
    }
    // 2) mem_val (fp16 out)
    {
        dim3 grid(O_ / TBN, M_ / TBM, H_);
        gemm_nt_f16<<<grid, 256>>>(memsh, MD, D_, Wvh, OD, D_,
                                   memvalh, MO, O_, bv, O_, D_, 0, 1);
    }
    // 3) softmax over O (row len 512) -> fp16
    softmax_rows_h<128><<<H_ * M_, 128>>>(memkey, memkeyh);

    // 3b) GT[h][o,m] = Wf_h @ mem_val[h]^T (fp16 out)
    {
        dim3 grid(M_ / TBN, O_ / TBM, H_);
        gemm_nt_f16<<<grid, 256>>>(Wfh, O_, (long long)H_ * O_, memvalh, MO, O_,
                                   GTh, MO, M_, nullptr, 0, O_, 0, 1);
    }

    // 4) att = kh @ mem_key^T (fp32 out)
    {
        dim3 grid(M_ / TBN, N_ / TBM, H_);
        gemm_nt_f16<<<grid, 256>>>(kh, 0, O_, memkeyh, MO, O_,
                                   att, NM, M_, nullptr, 0, O_, 0, 0);
    }
    // 5) softmax over M (row len 1024) -> fp16
    softmax_rows_h<256><<<H_ * N_, 256>>>(att, atth);

    // 6) fused: out[n,o] = sum_{h,m} att_w[h][n,m] * GT[h][o,m] + bf[o]
    {
        dim3 grid(O_ / TBN, N_ / TBM, 1);
        gemm_nt_f16<<<grid, 256>>>(atth, NM, M_, GTh, MO, M_,
                                   out, 0, O_, bf, 0, H_ * M_, M_, 0);
    }
}

// round 7
// speedup vs baseline: 7.5170x; 1.0148x over previous
#include <cuda_runtime.h>
#include <cuda_fp16.h>
#include <cstdint>
#include <cstddef>

// ---------------------------------------------------------------------------
// MultiHeadMemory: H=16, M=1024, D=512, O=512, N=16384
// fp16 mma.sync (m16n8k16) engine, fp32 accumulate. fp16 logits everywhere;
// softmax in place on fp16 with ex2.approx.f16x2 (1 MUFU per 2 elems).
//
//  0. convert inputs fp32 -> fp16 (one pass)
//  1. key_logits[h] = memsh[h] @ Wkh[h]^T + bk[h]  -> g_memkeyh (fp16)
//  2. mem_val[h]    = memsh[h] @ Wvh[h]^T + bv[h]  -> g_memvalh (fp16)
//  3. softmax rows of g_memkeyh (len 512), in place
//  3b. GT[h] = Wf_h @ mem_val[h]^T                 -> g_GTh [O,M] (fp16)
//  4. att[h] = kh @ mem_key[h]^T                   -> g_atth (fp16 logits)
//  5. softmax rows of g_atth (len 1024), in place
//  6. out = sum_h att_w[h] @ GT[h]^T + bf          (K = H*M fused, fp32 out)
// ---------------------------------------------------------------------------

#define H_  16
#define M_  1024
#define D_  512
#define O_  512
#define N_  16384

#define TBM 128
#define TBN 128
#define TBK 32          // halves per k-tile
#define ROWB 80         // bytes per SMEM row: 64 B data + 16 B pad

// fp16 scratch (static device globals; allocation-free kernel_launch)
__device__ __half g_kh[(size_t)N_ * O_];
__device__ __half g_memsh[(size_t)H_ * M_ * D_];
__device__ __half g_Wkh[(size_t)H_ * O_ * D_];
__device__ __half g_Wvh[(size_t)H_ * O_ * D_];
__device__ __half g_Wfh[(size_t)O_ * H_ * O_];
__device__ __half g_memkeyh[(size_t)H_ * M_ * O_];
__device__ __half g_memvalh[(size_t)H_ * M_ * O_];
__device__ __half g_GTh[(size_t)H_ * M_ * O_];       // [h][O][M]
__device__ __half g_atth[(size_t)H_ * N_ * M_];      // 0.5 GiB (logits->weights)

// ---------------------------------------------------------------------------
__device__ __forceinline__ float warpMax(float v) {
#pragma unroll
    for (int o = 16; o > 0; o >>= 1) v = fmaxf(v, __shfl_xor_sync(0xffffffffu, v, o));
    return v;
}
__device__ __forceinline__ float warpSum(float v) {
#pragma unroll
    for (int o = 16; o > 0; o >>= 1) v += __shfl_xor_sync(0xffffffffu, v, o);
    return v;
}
__device__ __forceinline__ void cp_async16(uint32_t smem_addr, const void* gptr) {
    asm volatile("cp.async.cg.shared.global [%0], [%1], 16;\n"
                 :: "r"(smem_addr), "l"(gptr));
}
__device__ __forceinline__ void ldmatrix_x4(uint32_t& r0, uint32_t& r1,
                                            uint32_t& r2, uint32_t& r3,
                                            uint32_t addr) {
    asm volatile("ldmatrix.sync.aligned.m8n8.x4.shared.b16 {%0,%1,%2,%3}, [%4];"
                 : "=r"(r0), "=r"(r1), "=r"(r2), "=r"(r3) : "r"(addr));
}
__device__ __forceinline__ uint32_t ex2_f16x2(uint32_t a) {
    uint32_t r;
    asm("ex2.approx.f16x2 %0, %1;" : "=r"(r) : "r"(a));
    return r;
}

// ---------------------------------------------------------------------------
// fp32 -> fp16 convert (8 floats / thread)
// ---------------------------------------------------------------------------
__global__ void __launch_bounds__(256) cvt_f32_f16(
    const float4* __restrict__ in, uint2* __restrict__ out, int n8)
{
    int i = blockIdx.x * 256 + threadIdx.x;
    if (i < n8) {
        float4 a = in[2 * i];
        float4 b = in[2 * i + 1];
        __half2 h0 = __floats2half2_rn(a.x, a.y);
        __half2 h1 = __floats2half2_rn(a.z, a.w);
        __half2 h2 = __floats2half2_rn(b.x, b.y);
        __half2 h3 = __floats2half2_rn(b.z, b.w);
        uint2 o0, o1;
        o0.x = *reinterpret_cast<uint32_t*>(&h0);
        o0.y = *reinterpret_cast<uint32_t*>(&h1);
        o1.x = *reinterpret_cast<uint32_t*>(&h2);
        o1.y = *reinterpret_cast<uint32_t*>(&h3);
        out[2 * i] = o0;
        out[2 * i + 1] = o1;
    }
}

// ---------------------------------------------------------------------------
// fp16 tensor-core GEMM NT, fp32 accumulate:
//   C[m, n] = sum_k A[m, k] * B[n, k]  (+ bias[n])
// A row ptr: A + z*aHead + m*lda + k              (kSplit == 0)
//            A + (k/kSplit)*aHead + m*lda + k%kSplit   (kSplit > 0, z==0)
// 128x128x32 CTA tile, 256 threads (8 warps, 4x2 / 32x64 warp tile),
// double-buffered cp.async, ldmatrix.x4 fragment loads.
// ---------------------------------------------------------------------------
__global__ void __launch_bounds__(256, 2) gemm_nt_f16(
    const __half* __restrict__ A, long long aHead, long long lda,
    const __half* __restrict__ B, long long bHead, long long ldb,
    void* __restrict__ Cv, long long cHead, long long ldc,
    const float* __restrict__ bias, long long biasHead,
    int K, int kSplit, int outHalf)
{
    const int z = blockIdx.z;
    if (kSplit == 0) {
        A += (long long)z * aHead;
        B += (long long)z * bHead;
    }
    if (bias) bias += (long long)z * biasHead;

    __shared__ __align__(16) char smraw[2 * 2 * TBM * ROWB];
    const uint32_t smBase = (uint32_t)__cvta_generic_to_shared(smraw);
    const uint32_t BUFB = 2 * TBM * ROWB;          // 20480
    const uint32_t BOFF = TBM * ROWB;              // 10240 (B tile offset)

    const int tid  = threadIdx.x;
    const int lane = tid & 31;
    const int warp = tid >> 5;
    const int g  = lane >> 2;
    const int tg = lane & 3;

    const int wm0 = (warp & 3) * 32;
    const int wn0 = (warp >> 2) * 64;

    const long long m0 = (long long)blockIdx.y * TBM;
    const long long n0 = (long long)blockIdx.x * TBN;

    const int pRow = tid >> 1;
    const int pCh  = (tid & 1) * 2;
    const uint32_t prodOff = (uint32_t)(pRow * ROWB + pCh * 16);

    const __half* aRowPtr = A + (m0 + pRow) * lda + pCh * 8;
    const __half* bRowPtr = B + (n0 + pRow) * ldb + pCh * 8;

    auto loadTile = [&](int kt, int buf) {
        const long long k0 = (long long)kt * TBK;
        long long kA, kB;
        if (kSplit > 0) {
            const long long kh = k0 / kSplit;
            const long long ko = k0 - kh * kSplit;
            kA = kh * aHead + ko;
            kB = kh * bHead + ko;
        } else {
            kA = k0; kB = k0;
        }
        const uint32_t ab = smBase + buf * BUFB + prodOff;
        const uint32_t bb = ab + BOFF;
#pragma unroll
        for (int c = 0; c < 2; ++c) {
            cp_async16(ab + c * 16, aRowPtr + kA + c * 8);
            cp_async16(bb + c * 16, bRowPtr + kB + c * 8);
        }
        asm volatile("cp.async.commit_group;\n" ::);
    };

    const int mat  = lane >> 3;
    const int row8 = lane & 7;
    uint32_t aOff[2], bOff[4];
#pragma unroll
    for (int i = 0; i < 2; ++i)
        aOff[i] = (uint32_t)((wm0 + i * 16 + (mat & 1) * 8 + row8) * ROWB
                             + (mat >> 1) * 16);
#pragma unroll
    for (int p = 0; p < 4; ++p)
        bOff[p] = (uint32_t)(BOFF + (wn0 + (2 * p + (mat >> 1)) * 8 + row8) * ROWB
                             + (mat & 1) * 16);

    float acc[2][8][4];
#pragma unroll
    for (int i = 0; i < 2; ++i)
#pragma unroll
        for (int j = 0; j < 8; ++j)
#pragma unroll
            for (int r = 0; r < 4; ++r) acc[i][j][r] = 0.f;

    const int nIter = K / TBK;
    loadTile(0, 0);

    for (int kt = 0; kt < nIter; ++kt) {
        asm volatile("cp.async.wait_group 0;\n" ::);
        __syncthreads();

        if (kt + 1 < nIter) loadTile(kt + 1, (kt + 1) & 1);

        const uint32_t base = smBase + (uint32_t)(kt & 1) * BUFB;
#pragma unroll
        for (int ks = 0; ks < 2; ++ks) {
            const uint32_t ksb = base + ks * 32;
            uint32_t af[2][4];
#pragma unroll
            for (int i = 0; i < 2; ++i)
                ldmatrix_x4(af[i][0], af[i][1], af[i][2], af[i][3], ksb + aOff[i]);
            uint32_t bf[8][2];
#pragma unroll
            for (int p = 0; p < 4; ++p)
                ldmatrix_x4(bf[2 * p][0], bf[2 * p][1],
                            bf[2 * p + 1][0], bf[2 * p + 1][1], ksb + bOff[p]);
#pragma unroll
            for (int i = 0; i < 2; ++i) {
#pragma unroll
                for (int j = 0; j < 8; ++j) {
                    asm volatile(
                        "mma.sync.aligned.m16n8k16.row.col.f32.f16.f16.f32 "
                        "{%0,%1,%2,%3}, {%4,%5,%6,%7}, {%8,%9}, {%0,%1,%2,%3};"
                        : "+f"(acc[i][j][0]), "+f"(acc[i][j][1]),
                          "+f"(acc[i][j][2]), "+f"(acc[i][j][3])
                        : "r"(af[i][0]), "r"(af[i][1]), "r"(af[i][2]), "r"(af[i][3]),
                          "r"(bf[j][0]), "r"(bf[j][1]));
                }
            }
        }
        __syncthreads();
    }

    const long long cBase = (long long)z * cHead;
#pragma unroll
    for (int i = 0; i < 2; ++i) {
        const long long r0 = m0 + wm0 + i * 16 + g;
#pragma unroll
        for (int j = 0; j < 8; ++j) {
            const long long cc = n0 + wn0 + j * 8 + 2 * tg;
            float b0 = 0.f, b1 = 0.f;
            if (bias) { b0 = bias[cc]; b1 = bias[cc + 1]; }
            float v00 = acc[i][j][0] + b0, v01 = acc[i][j][1] + b1;
            float v10 = acc[i][j][2] + b0, v11 = acc[i][j][3] + b1;
            if (outHalf) {
                __half* C = (__half*)Cv + cBase;
                __half2 h0 = __floats2half2_rn(v00, v01);
                __half2 h1 = __floats2half2_rn(v10, v11);
                *reinterpret_cast<__half2*>(C + r0 * ldc + cc) = h0;
                *reinterpret_cast<__half2*>(C + (r0 + 8) * ldc + cc) = h1;
            } else {
                float* C = (float*)Cv + cBase;
                *reinterpret_cast<float2*>(C + r0 * ldc + cc) = make_float2(v00, v01);
                *reinterpret_cast<float2*>(C + (r0 + 8) * ldc + cc) = make_float2(v10, v11);
            }
        }
    }
}

// ---------------------------------------------------------------------------
// In-place fp16 row softmax with ex2.approx.f16x2.
// ROWLEN halves per row; THREADS = ROWLEN/4; each thread owns 4 halves (uint2).
// Max + sum reductions in fp32; normalization applied in fp32 then packed.
// ---------------------------------------------------------------------------
template <int ROWLEN>
__global__ void __launch_bounds__(ROWLEN / 4) softmax_h(__half* __restrict__ data)
{
    constexpr int THREADS = ROWLEN / 4;
    constexpr int NW = THREADS / 32;
    const long long row = blockIdx.x;
    uint2* p = reinterpret_cast<uint2*>(data + row * (long long)ROWLEN);
    uint2 u = p[threadIdx.x];

    __half2 h0 = *reinterpret_cast<__half2*>(&u.x);
    __half2 h1 = *reinterpret_cast<__half2*>(&u.y);
    float2 f0 = __half22float2(h0);
    float2 f1 = __half22float2(h1);

    const int warp = threadIdx.x >> 5;
    const int lane = threadIdx.x & 31;
    __shared__ float sred[NW];

    float mx = fmaxf(fmaxf(f0.x, f0.y), fmaxf(f1.x, f1.y));
    mx = warpMax(mx);
    if (lane == 0) sred[warp] = mx;
    __syncthreads();
    if (warp == 0) {
        float t = (lane < NW) ? sred[lane] : -3.4e38f;
        t = warpMax(t);
        if (lane == 0) sred[0] = t;
    }
    __syncthreads();
    mx = sred[0];
    __syncthreads();   // protect sred before reuse for sum

    // exp via ex2.approx.f16x2: arg computed in fp32, packed to half2
    const float L2E = 1.44269504f;
    __half2 a0 = __floats2half2_rn((f0.x - mx) * L2E, (f0.y - mx) * L2E);
    __half2 a1 = __floats2half2_rn((f1.x - mx) * L2E, (f1.y - mx) * L2E);
    uint32_t e0 = ex2_f16x2(*reinterpret_cast<uint32_t*>(&a0));
    uint32_t e1 = ex2_f16x2(*reinterpret_cast<uint32_t*>(&a1));
    float2 E0 = __half22float2(*reinterpret_cast<__half2*>(&e0));
    float2 E1 = __half22float2(*reinterpret_cast<__half2*>(&e1));

    float s = E0.x + E0.y + E1.x + E1.y;
    s = warpSum(s);
    if (lane == 0) sred[warp] = s;
    __syncthreads();
    if (warp == 0) {
        float t = (lane < NW) ? sred[lane] : 0.f;
        t = warpSum(t);
        if (lane == 0) sred[0] = t;
    }
    __syncthreads();
    const float inv = 1.0f / sred[0];

    __half2 w0 = __floats2half2_rn(E0.x * inv, E0.y * inv);
    __half2 w1 = __floats2half2_rn(E1.x * inv, E1.y * inv);
    uint2 o;
    o.x = *reinterpret_cast<uint32_t*>(&w0);
    o.y = *reinterpret_cast<uint32_t*>(&w1);
    p[threadIdx.x] = o;
}

// ---------------------------------------------------------------------------
// Launch
// ---------------------------------------------------------------------------
extern "C" void kernel_launch(void* const* d_in, const int* in_sizes, int n_in,
                              void* d_out, int out_size)
{
    const float* k_in = (const float*)d_in[0];   // [N, O]
    const float* mems = (const float*)d_in[1];   // [H, M, D]
    const float* Wk   = (const float*)d_in[2];   // [H, O, D]
    const float* bk   = (const float*)d_in[3];   // [H, O]
    const float* Wv   = (const float*)d_in[4];   // [H, O, D]
    const float* bv   = (const float*)d_in[5];   // [H, O]
    const float* Wf   = (const float*)d_in[6];   // [O, H*O]
    const float* bf   = (const float*)d_in[7];   // [O]
    float* out = (float*)d_out;                  // [N, O]

    __half *kh, *memsh, *Wkh, *Wvh, *Wfh, *memkeyh, *memvalh, *GTh, *atth;
    cudaGetSymbolAddress((void**)&kh,      g_kh);
    cudaGetSymbolAddress((void**)&memsh,   g_memsh);
    cudaGetSymbolAddress((void**)&Wkh,     g_Wkh);
    cudaGetSymbolAddress((void**)&Wvh,     g_Wvh);
    cudaGetSymbolAddress((void**)&Wfh,     g_Wfh);
    cudaGetSymbolAddress((void**)&memkeyh, g_memkeyh);
    cudaGetSymbolAddress((void**)&memvalh, g_memvalh);
    cudaGetSymbolAddress((void**)&GTh,     g_GTh);
    cudaGetSymbolAddress((void**)&atth,    g_atth);

    const long long MD = (long long)M_ * D_;
    const long long OD = (long long)O_ * D_;
    const long long MO = (long long)M_ * O_;
    const long long NM = (long long)N_ * M_;

    // 0) convert inputs to fp16
    {
        auto cv = [&](const float* src, __half* dst, long long n) {
            int n8 = (int)(n / 8);
            cvt_f32_f16<<<(n8 + 255) / 256, 256>>>(
                (const float4*)src, (uint2*)dst, n8);
        };
        cv(k_in, kh,    (long long)N_ * O_);
        cv(mems, memsh, (long long)H_ * M_ * D_);
        cv(Wk,  Wkh,    (long long)H_ * O_ * D_);
        cv(Wv,  Wvh,    (long long)H_ * O_ * D_);
        cv(Wf,  Wfh,    (long long)O_ * H_ * O_);
    }

    // 1) key logits (fp16 out): memkeyh[h][m,o] = memsh[h] @ Wkh[h]^T + bk[h]
    {
        dim3 grid(O_ / TBN, M_ / TBM, H_);
        gemm_nt_f16<<<grid, 256>>>(memsh, MD, D_, Wkh, OD, D_,
                                   memkeyh, MO, O_, bk, O_, D_, 0, 1);
    }
    // 2) mem_val (fp16 out)
    {
        dim3 grid(O_ / TBN, M_ / TBM, H_);
        gemm_nt_f16<<<grid, 256>>>(memsh, MD, D_, Wvh, OD, D_,
                                   memvalh, MO, O_, bv, O_, D_, 0, 1);
    }
    // 3) softmax over O (row len 512), in place on fp16
    softmax_h<512><<<H_ * M_, 128>>>(memkeyh);

    // 3b) GT[h][o,m] = Wf_h @ mem_val[h]^T (fp16 out)
    {
        dim3 grid(M_ / TBN, O_ / TBM, H_);
        gemm_nt_f16<<<grid, 256>>>(Wfh, O_, (long long)H_ * O_, memvalh, MO, O_,
                                   GTh, MO, M_, nullptr, 0, O_, 0, 1);
    }

    // 4) att logits (fp16 out, straight into atth)
    {
        dim3 grid(M_ / TBN, N_ / TBM, H_);
        gemm_nt_f16<<<grid, 256>>>(kh, 0, O_, memkeyh, MO, O_,
                                   atth, NM, M_, nullptr, 0, O_, 0, 1);
    }
    // 5) softmax over M (row len 1024), in place on fp16
    softmax_h<1024><<<H_ * N_, 256>>>(atth);

    // 6) fused: out[n,o] = sum_{h,m} att_w[h][n,m] * GT[h][o,m] + bf[o]
    {
        dim3 grid(O_ / TBN, N_ / TBM, 1);
        gemm_nt_f16<<<grid, 256>>>(atth, NM, M_, GTh, MO, M_,
                                   out, 0, O_, bf, 0, H_ * M_, M_, 0);
    }
}

// round 8
// speedup vs baseline: 7.5425x; 1.0034x over previous
#include <cuda_runtime.h>
#include <cuda_fp16.h>
#include <cstdint>
#include <cstddef>

// ---------------------------------------------------------------------------
// MultiHeadMemory: H=16, M=1024, D=512, O=512, N=16384
// fp16 mma.sync (m16n8k16) engine, fp32 accumulate.
// R8: 3-stage cp.async pipeline, prefetch depth 2, ONE __syncthreads per
// k-tile (was 2-stage / depth 1 / two baps). Everything else as R7.
//
//  0. convert inputs fp32 -> fp16 (one pass)
//  1. key_logits[h] = memsh[h] @ Wkh[h]^T + bk[h]  -> g_memkeyh (fp16)
//  2. mem_val[h]    = memsh[h] @ Wvh[h]^T + bv[h]  -> g_memvalh (fp16)
//  3. softmax rows of g_memkeyh (len 512), in place
//  3b. GT[h] = Wf_h @ mem_val[h]^T                 -> g_GTh [O,M] (fp16)
//  4. att[h] = kh @ mem_key[h]^T                   -> g_atth (fp16 logits)
//  5. softmax rows of g_atth (len 1024), in place
//  6. out = sum_h att_w[h] @ GT[h]^T + bf          (K = H*M fused, fp32 out)
// ---------------------------------------------------------------------------

#define H_  16
#define M_  1024
#define D_  512
#define O_  512
#define N_  16384

#define TBM 128
#define TBN 128
#define TBK 32          // halves per k-tile
#define ROWB 80         // bytes per SMEM row: 64 B data + 16 B pad
#define NSTG 3
#define STGB (2 * TBM * ROWB)            // A+B per stage = 20480 B
#define SMEM_DYN (NSTG * STGB)           // 61440 B

// fp16 scratch (static device globals; allocation-free kernel_launch)
__device__ __half g_kh[(size_t)N_ * O_];
__device__ __half g_memsh[(size_t)H_ * M_ * D_];
__device__ __half g_Wkh[(size_t)H_ * O_ * D_];
__device__ __half g_Wvh[(size_t)H_ * O_ * D_];
__device__ __half g_Wfh[(size_t)O_ * H_ * O_];
__device__ __half g_memkeyh[(size_t)H_ * M_ * O_];
__device__ __half g_memvalh[(size_t)H_ * M_ * O_];
__device__ __half g_GTh[(size_t)H_ * M_ * O_];       // [h][O][M]
__device__ __half g_atth[(size_t)H_ * N_ * M_];      // 0.5 GiB

// ---------------------------------------------------------------------------
__device__ __forceinline__ float warpMax(float v) {
#pragma unroll
    for (int o = 16; o > 0; o >>= 1) v = fmaxf(v, __shfl_xor_sync(0xffffffffu, v, o));
    return v;
}
__device__ __forceinline__ float warpSum(float v) {
#pragma unroll
    for (int o = 16; o > 0; o >>= 1) v += __shfl_xor_sync(0xffffffffu, v, o);
    return v;
}
__device__ __forceinline__ void cp_async16(uint32_t smem_addr, const void* gptr) {
    asm volatile("cp.async.cg.shared.global [%0], [%1], 16;\n"
                 :: "r"(smem_addr), "l"(gptr));
}
__device__ __forceinline__ void ldmatrix_x4(uint32_t& r0, uint32_t& r1,
                                            uint32_t& r2, uint32_t& r3,
                                            uint32_t addr) {
    asm volatile("ldmatrix.sync.aligned.m8n8.x4.shared.b16 {%0,%1,%2,%3}, [%4];"
                 : "=r"(r0), "=r"(r1), "=r"(r2), "=r"(r3) : "r"(addr));
}
__device__ __forceinline__ uint32_t ex2_f16x2(uint32_t a) {
    uint32_t r;
    asm("ex2.approx.f16x2 %0, %1;" : "=r"(r) : "r"(a));
    return r;
}

// ---------------------------------------------------------------------------
// fp32 -> fp16 convert (8 floats / thread)
// ---------------------------------------------------------------------------
__global__ void __launch_bounds__(256) cvt_f32_f16(
    const float4* __restrict__ in, uint2* __restrict__ out, int n8)
{
    int i = blockIdx.x * 256 + threadIdx.x;
    if (i < n8) {
        float4 a = in[2 * i];
        float4 b = in[2 * i + 1];
        __half2 h0 = __floats2half2_rn(a.x, a.y);
        __half2 h1 = __floats2half2_rn(a.z, a.w);
        __half2 h2 = __floats2half2_rn(b.x, b.y);
        __half2 h3 = __floats2half2_rn(b.z, b.w);
        uint2 o0, o1;
        o0.x = *reinterpret_cast<uint32_t*>(&h0);
        o0.y = *reinterpret_cast<uint32_t*>(&h1);
        o1.x = *reinterpret_cast<uint32_t*>(&h2);
        o1.y = *reinterpret_cast<uint32_t*>(&h3);
        out[2 * i] = o0;
        out[2 * i + 1] = o1;
    }
}

// ---------------------------------------------------------------------------
// fp16 tensor-core GEMM NT, fp32 accumulate:
//   C[m, n] = sum_k A[m, k] * B[n, k]  (+ bias[n])
// A row ptr: A + z*aHead + m*lda + k              (kSplit == 0)
//            A + (k/kSplit)*aHead + m*lda + k%kSplit   (kSplit > 0, z==0)
// 128x128x32 CTA tile, 256 threads (8 warps, 4x2 / 32x64 warp tile),
// 3-stage cp.async pipeline, single barrier per k-tile, ldmatrix.x4 frags.
// ---------------------------------------------------------------------------
__global__ void __launch_bounds__(256, 2) gemm_nt_f16(
    const __half* __restrict__ A, long long aHead, long long lda,
    const __half* __restrict__ B, long long bHead, long long ldb,
    void* __restrict__ Cv, long long cHead, long long ldc,
    const float* __restrict__ bias, long long biasHead,
    int K, int kSplit, int outHalf)
{
    const int z = blockIdx.z;
    if (kSplit == 0) {
        A += (long long)z * aHead;
        B += (long long)z * bHead;
    }
    if (bias) bias += (long long)z * biasHead;

    extern __shared__ __align__(16) char smraw[];
    const uint32_t smBase = (uint32_t)__cvta_generic_to_shared(smraw);
    const uint32_t BOFF = TBM * ROWB;              // B tile offset within stage

    const int tid  = threadIdx.x;
    const int lane = tid & 31;
    const int warp = tid >> 5;
    const int g  = lane >> 2;
    const int tg = lane & 3;

    const int wm0 = (warp & 3) * 32;
    const int wn0 = (warp >> 2) * 64;

    const long long m0 = (long long)blockIdx.y * TBM;
    const long long n0 = (long long)blockIdx.x * TBN;

    const int pRow = tid >> 1;
    const int pCh  = (tid & 1) * 2;
    const uint32_t prodOff = (uint32_t)(pRow * ROWB + pCh * 16);

    const __half* aRowPtr = A + (m0 + pRow) * lda + pCh * 8;
    const __half* bRowPtr = B + (n0 + pRow) * ldb + pCh * 8;

    auto loadTile = [&](int kt, int stg) {
        const long long k0 = (long long)kt * TBK;
        long long kA, kB;
        if (kSplit > 0) {
            const long long kh = k0 / kSplit;
            const long long ko = k0 - kh * kSplit;
            kA = kh * aHead + ko;
            kB = kh * bHead + ko;
        } else {
            kA = k0; kB = k0;
        }
        const uint32_t ab = smBase + (uint32_t)stg * STGB + prodOff;
        const uint32_t bb = ab + BOFF;
#pragma unroll
        for (int c = 0; c < 2; ++c) {
            cp_async16(ab + c * 16, aRowPtr + kA + c * 8);
            cp_async16(bb + c * 16, bRowPtr + kB + c * 8);
        }
        asm volatile("cp.async.commit_group;\n" ::);
    };

    const int mat  = lane >> 3;
    const int row8 = lane & 7;
    uint32_t aOff[2], bOff[4];
#pragma unroll
    for (int i = 0; i < 2; ++i)
        aOff[i] = (uint32_t)((wm0 + i * 16 + (mat & 1) * 8 + row8) * ROWB
                             + (mat >> 1) * 16);
#pragma unroll
    for (int p = 0; p < 4; ++p)
        bOff[p] = (uint32_t)(BOFF + (wn0 + (2 * p + (mat >> 1)) * 8 + row8) * ROWB
                             + (mat & 1) * 16);

    float acc[2][8][4];
#pragma unroll
    for (int i = 0; i < 2; ++i)
#pragma unroll
        for (int j = 0; j < 8; ++j)
#pragma unroll
            for (int r = 0; r < 4; ++r) acc[i][j][r] = 0.f;

    const int nIter = K / TBK;
    loadTile(0, 0);
    if (nIter > 1) loadTile(1, 1);

    int stg = 0;
    for (int kt = 0; kt < nIter; ++kt) {
        // Tile kt must be resident. With depth-2 prefetch the newest group
        // (kt+1) may still be in flight except on the last iteration.
        if (kt + 1 < nIter) {
            asm volatile("cp.async.wait_group 1;\n" ::);
        } else {
            asm volatile("cp.async.wait_group 0;\n" ::);
        }
        __syncthreads();   // also orders compute(kt-1) before load into its stage

        if (kt + 2 < nIter) {
            int ns = stg + 2; if (ns >= NSTG) ns -= NSTG;
            loadTile(kt + 2, ns);
        }

        const uint32_t base = smBase + (uint32_t)stg * STGB;
#pragma unroll
        for (int ks = 0; ks < 2; ++ks) {
            const uint32_t ksb = base + ks * 32;
            uint32_t af[2][4];
#pragma unroll
            for (int i = 0; i < 2; ++i)
                ldmatrix_x4(af[i][0], af[i][1], af[i][2], af[i][3], ksb + aOff[i]);
            uint32_t bf[8][2];
#pragma unroll
            for (int p = 0; p < 4; ++p)
                ldmatrix_x4(bf[2 * p][0], bf[2 * p][1],
                            bf[2 * p + 1][0], bf[2 * p + 1][1], ksb + bOff[p]);
#pragma unroll
            for (int i = 0; i < 2; ++i) {
#pragma unroll
                for (int j = 0; j < 8; ++j) {
                    asm volatile(
                        "mma.sync.aligned.m16n8k16.row.col.f32.f16.f16.f32 "
                        "{%0,%1,%2,%3}, {%4,%5,%6,%7}, {%8,%9}, {%0,%1,%2,%3};"
                        : "+f"(acc[i][j][0]), "+f"(acc[i][j][1]),
                          "+f"(acc[i][j][2]), "+f"(acc[i][j][3])
                        : "r"(af[i][0]), "r"(af[i][1]), "r"(af[i][2]), "r"(af[i][3]),
                          "r"(bf[j][0]), "r"(bf[j][1]));
                }
            }
        }
        ++stg; if (stg == NSTG) stg = 0;
    }

    const long long cBase = (long long)z * cHead;
#pragma unroll
    for (int i = 0; i < 2; ++i) {
        const long long r0 = m0 + wm0 + i * 16 + g;
#pragma unroll
        for (int j = 0; j < 8; ++j) {
            const long long cc = n0 + wn0 + j * 8 + 2 * tg;
            float b0 = 0.f, b1 = 0.f;
            if (bias) { b0 = bias[cc]; b1 = bias[cc + 1]; }
            float v00 = acc[i][j][0] + b0, v01 = acc[i][j][1] + b1;
            float v10 = acc[i][j][2] + b0, v11 = acc[i][j][3] + b1;
            if (outHalf) {
                __half* C = (__half*)Cv + cBase;
                __half2 h0 = __floats2half2_rn(v00, v01);
                __half2 h1 = __floats2half2_rn(v10, v11);
                *reinterpret_cast<__half2*>(C + r0 * ldc + cc) = h0;
                *reinterpret_cast<__half2*>(C + (r0 + 8) * ldc + cc) = h1;
            } else {
                float* C = (float*)Cv + cBase;
                *reinterpret_cast<float2*>(C + r0 * ldc + cc) = make_float2(v00, v01);
                *reinterpret_cast<float2*>(C + (r0 + 8) * ldc + cc) = make_float2(v10, v11);
            }
        }
    }
}

// ---------------------------------------------------------------------------
// In-place fp16 row softmax with ex2.approx.f16x2.
// ---------------------------------------------------------------------------
template <int ROWLEN>
__global__ void __launch_bounds__(ROWLEN / 4) softmax_h(__half* __restrict__ data)
{
    constexpr int THREADS = ROWLEN / 4;
    constexpr int NW = THREADS / 32;
    const long long row = blockIdx.x;
    uint2* p = reinterpret_cast<uint2*>(data + row * (long long)ROWLEN);
    uint2 u = p[threadIdx.x];

    __half2 h0 = *reinterpret_cast<__half2*>(&u.x);
    __half2 h1 = *reinterpret_cast<__half2*>(&u.y);
    float2 f0 = __half22float2(h0);
    float2 f1 = __half22float2(h1);

    const int warp = threadIdx.x >> 5;
    const int lane = threadIdx.x & 31;
    __shared__ float sred[NW];

    float mx = fmaxf(fmaxf(f0.x, f0.y), fmaxf(f1.x, f1.y));
    mx = warpMax(mx);
    if (lane == 0) sred[warp] = mx;
    __syncthreads();
    if (warp == 0) {
        float t = (lane < NW) ? sred[lane] : -3.4e38f;
        t = warpMax(t);
        if (lane == 0) sred[0] = t;
    }
    __syncthreads();
    mx = sred[0];
    __syncthreads();

    const float L2E = 1.44269504f;
    __half2 a0 = __floats2half2_rn((f0.x - mx) * L2E, (f0.y - mx) * L2E);
    __half2 a1 = __floats2half2_rn((f1.x - mx) * L2E, (f1.y - mx) * L2E);
    uint32_t e0 = ex2_f16x2(*reinterpret_cast<uint32_t*>(&a0));
    uint32_t e1 = ex2_f16x2(*reinterpret_cast<uint32_t*>(&a1));
    float2 E0 = __half22float2(*reinterpret_cast<__half2*>(&e0));
    float2 E1 = __half22float2(*reinterpret_cast<__half2*>(&e1));

    float s = E0.x + E0.y + E1.x + E1.y;
    s = warpSum(s);
    if (lane == 0) sred[warp] = s;
    __syncthreads();
    if (warp == 0) {
        float t = (lane < NW) ? sred[lane] : 0.f;
        t = warpSum(t);
        if (lane == 0) sred[0] = t;
    }
    __syncthreads();
    const float inv = 1.0f / sred[0];

    __half2 w0 = __floats2half2_rn(E0.x * inv, E0.y * inv);
    __half2 w1 = __floats2half2_rn(E1.x * inv, E1.y * inv);
    uint2 o;
    o.x = *reinterpret_cast<uint32_t*>(&w0);
    o.y = *reinterpret_cast<uint32_t*>(&w1);
    p[threadIdx.x] = o;
}

// ---------------------------------------------------------------------------
// Launch
// ---------------------------------------------------------------------------
extern "C" void kernel_launch(void* const* d_in, const int* in_sizes, int n_in,
                              void* d_out, int out_size)
{
    const float* k_in = (const float*)d_in[0];   // [N, O]
    const float* mems = (const float*)d_in[1];   // [H, M, D]
    const float* Wk   = (const float*)d_in[2];   // [H, O, D]
    const float* bk   = (const float*)d_in[3];   // [H, O]
    const float* Wv   = (const float*)d_in[4];   // [H, O, D]
    const float* bv   = (const float*)d_in[5];   // [H, O]
    const float* Wf   = (const float*)d_in[6];   // [O, H*O]
    const float* bf   = (const float*)d_in[7];   // [O]
    float* out = (float*)d_out;                  // [N, O]

    cudaFuncSetAttribute(gemm_nt_f16,
                         cudaFuncAttributeMaxDynamicSharedMemorySize, SMEM_DYN);

    __half *kh, *memsh, *Wkh, *Wvh, *Wfh, *memkeyh, *memvalh, *GTh, *atth;
    cudaGetSymbolAddress((void**)&kh,      g_kh);
    cudaGetSymbolAddress((void**)&memsh,   g_memsh);
    cudaGetSymbolAddress((void**)&Wkh,     g_Wkh);
    cudaGetSymbolAddress((void**)&Wvh,     g_Wvh);
    cudaGetSymbolAddress((void**)&Wfh,     g_Wfh);
    cudaGetSymbolAddress((void**)&memkeyh, g_memkeyh);
    cudaGetSymbolAddress((void**)&memvalh, g_memvalh);
    cudaGetSymbolAddress((void**)&GTh,     g_GTh);
    cudaGetSymbolAddress((void**)&atth,    g_atth);

    const long long MD = (long long)M_ * D_;
    const long long OD = (long long)O_ * D_;
    const long long MO = (long long)M_ * O_;
    const long long NM = (long long)N_ * M_;

    // 0) convert inputs to fp16
    {
        auto cv = [&](const float* src, __half* dst, long long n) {
            int n8 = (int)(n / 8);
            cvt_f32_f16<<<(n8 + 255) / 256, 256>>>(
                (const float4*)src, (uint2*)dst, n8);
        };
        cv(k_in, kh,    (long long)N_ * O_);
        cv(mems, memsh, (long long)H_ * M_ * D_);
        cv(Wk,  Wkh,    (long long)H_ * O_ * D_);
        cv(Wv,  Wvh,    (long long)H_ * O_ * D_);
        cv(Wf,  Wfh,    (long long)O_ * H_ * O_);
    }

    // 1) key logits (fp16 out)
    {
        dim3 grid(O_ / TBN, M_ / TBM, H_);
        gemm_nt_f16<<<grid, 256, SMEM_DYN>>>(memsh, MD, D_, Wkh, OD, D_,
                                             memkeyh, MO, O_, bk, O_, D_, 0, 1);
    }
    // 2) mem_val (fp16 out)
    {
        dim3 grid(O_ / TBN, M_ / TBM, H_);
        gemm_nt_f16<<<grid, 256, SMEM_DYN>>>(memsh, MD, D_, Wvh, OD, D_,
                                             memvalh, MO, O_, bv, O_, D_, 0, 1);
    }
    // 3) softmax over O (row len 512), in place on fp16
    softmax_h<512><<<H_ * M_, 128>>>(memkeyh);

    // 3b) GT[h][o,m] = Wf_h @ mem_val[h]^T (fp16 out)
    {
        dim3 grid(M_ / TBN, O_ / TBM, H_);
        gemm_nt_f16<<<grid, 256, SMEM_DYN>>>(Wfh, O_, (long long)H_ * O_,
                                             memvalh, MO, O_,
                                             GTh, MO, M_, nullptr, 0, O_, 0, 1);
    }

    // 4) att logits (fp16 out, straight into atth)
    {
        dim3 grid(M_ / TBN, N_ / TBM, H_);
        gemm_nt_f16<<<grid, 256, SMEM_DYN>>>(kh, 0, O_, memkeyh, MO, O_,
                                             atth, NM, M_, nullptr, 0, O_, 0, 1);
    }
    // 5) softmax over M (row len 1024), in place on fp16
    softmax_h<1024><<<H_ * N_, 256>>>(atth);

    // 6) fused: out[n,o] = sum_{h,m} att_w[h][n,m] * GT[h][o,m] + bf[o]
    {
        dim3 grid(O_ / TBN, N_ / TBM, 1);
        gemm_nt_f16<<<grid, 256, SMEM_DYN>>>(atth, NM, M_, GTh, MO, M_,
                                             out, 0, O_, bf, 0, H_ * M_, M_, 0);
    }
}

// round 9
// speedup vs baseline: 7.6326x; 1.0119x over previous
#include <cuda_runtime.h>
#include <cuda_fp16.h>
#include <cstdint>
#include <cstddef>

// ---------------------------------------------------------------------------
// MultiHeadMemory: H=16, M=1024, D=512, O=512, N=16384
// fp16 mma.sync (m16n8k16) engine, fp32 accumulate — at the legacy-HMMA
// roofline (~288 TF/s). R9: multi-stream DAG inside graph capture to overlap
// the independent side chains with the critical spine (kernels unchanged).
//
// spine (s0): cvt mems, cvt Wk -> GEMM1 -> softmax3 -> [eK] GEMM4
//             -> softmax5 -> [e3b] GEMM6
// sB:  [fork] cvt Wv -> [eMems] GEMM2 -> [eWf] GEMM3b -> e3b
// sC:  [fork] cvt k -> eK ; cvt Wf -> eWf
// ---------------------------------------------------------------------------

#define H_  16
#define M_  1024
#define D_  512
#define O_  512
#define N_  16384

#define TBM 128
#define TBN 128
#define TBK 32          // halves per k-tile
#define ROWB 80         // bytes per SMEM row: 64 B data + 16 B pad
#define NSTG 3
#define STGB (2 * TBM * ROWB)            // A+B per stage = 20480 B
#define SMEM_DYN (NSTG * STGB)           // 61440 B

// fp16 scratch (static device globals; allocation-free kernel_launch)
__device__ __half g_kh[(size_t)N_ * O_];
__device__ __half g_memsh[(size_t)H_ * M_ * D_];
__device__ __half g_Wkh[(size_t)H_ * O_ * D_];
__device__ __half g_Wvh[(size_t)H_ * O_ * D_];
__device__ __half g_Wfh[(size_t)O_ * H_ * O_];
__device__ __half g_memkeyh[(size_t)H_ * M_ * O_];
__device__ __half g_memvalh[(size_t)H_ * M_ * O_];
__device__ __half g_GTh[(size_t)H_ * M_ * O_];       // [h][O][M]
__device__ __half g_atth[(size_t)H_ * N_ * M_];      // 0.5 GiB

// ---------------------------------------------------------------------------
__device__ __forceinline__ float warpMax(float v) {
#pragma unroll
    for (int o = 16; o > 0; o >>= 1) v = fmaxf(v, __shfl_xor_sync(0xffffffffu, v, o));
    return v;
}
__device__ __forceinline__ float warpSum(float v) {
#pragma unroll
    for (int o = 16; o > 0; o >>= 1) v += __shfl_xor_sync(0xffffffffu, v, o);
    return v;
}
__device__ __forceinline__ void cp_async16(uint32_t smem_addr, const void* gptr) {
    asm volatile("cp.async.cg.shared.global [%0], [%1], 16;\n"
                 :: "r"(smem_addr), "l"(gptr));
}
__device__ __forceinline__ void ldmatrix_x4(uint32_t& r0, uint32_t& r1,
                                            uint32_t& r2, uint32_t& r3,
                                            uint32_t addr) {
    asm volatile("ldmatrix.sync.aligned.m8n8.x4.shared.b16 {%0,%1,%2,%3}, [%4];"
                 : "=r"(r0), "=r"(r1), "=r"(r2), "=r"(r3) : "r"(addr));
}
__device__ __forceinline__ uint32_t ex2_f16x2(uint32_t a) {
    uint32_t r;
    asm("ex2.approx.f16x2 %0, %1;" : "=r"(r) : "r"(a));
    return r;
}

// ---------------------------------------------------------------------------
// fp32 -> fp16 convert (8 floats / thread)
// ---------------------------------------------------------------------------
__global__ void __launch_bounds__(256) cvt_f32_f16(
    const float4* __restrict__ in, uint2* __restrict__ out, int n8)
{
    int i = blockIdx.x * 256 + threadIdx.x;
    if (i < n8) {
        float4 a = in[2 * i];
        float4 b = in[2 * i + 1];
        __half2 h0 = __floats2half2_rn(a.x, a.y);
        __half2 h1 = __floats2half2_rn(a.z, a.w);
        __half2 h2 = __floats2half2_rn(b.x, b.y);
        __half2 h3 = __floats2half2_rn(b.z, b.w);
        uint2 o0, o1;
        o0.x = *reinterpret_cast<uint32_t*>(&h0);
        o0.y = *reinterpret_cast<uint32_t*>(&h1);
        o1.x = *reinterpret_cast<uint32_t*>(&h2);
        o1.y = *reinterpret_cast<uint32_t*>(&h3);
        out[2 * i] = o0;
        out[2 * i + 1] = o1;
    }
}

// ---------------------------------------------------------------------------
// fp16 tensor-core GEMM NT, fp32 accumulate (identical to R8):
//   C[m, n] = sum_k A[m, k] * B[n, k]  (+ bias[n])
// 128x128x32 CTA tile, 256 threads (8 warps, 4x2 / 32x64 warp tile),
// 3-stage cp.async pipeline, single barrier per k-tile, ldmatrix.x4 frags.
// ---------------------------------------------------------------------------
__global__ void __launch_bounds__(256, 2) gemm_nt_f16(
    const __half* __restrict__ A, long long aHead, long long lda,
    const __half* __restrict__ B, long long bHead, long long ldb,
    void* __restrict__ Cv, long long cHead, long long ldc,
    const float* __restrict__ bias, long long biasHead,
    int K, int kSplit, int outHalf)
{
    const int z = blockIdx.z;
    if (kSplit == 0) {
        A += (long long)z * aHead;
        B += (long long)z * bHead;
    }
    if (bias) bias += (long long)z * biasHead;

    extern __shared__ __align__(16) char smraw[];
    const uint32_t smBase = (uint32_t)__cvta_generic_to_shared(smraw);
    const uint32_t BOFF = TBM * ROWB;

    const int tid  = threadIdx.x;
    const int lane = tid & 31;
    const int warp = tid >> 5;
    const int g  = lane >> 2;
    const int tg = lane & 3;

    const int wm0 = (warp & 3) * 32;
    const int wn0 = (warp >> 2) * 64;

    const long long m0 = (long long)blockIdx.y * TBM;
    const long long n0 = (long long)blockIdx.x * TBN;

    const int pRow = tid >> 1;
    const int pCh  = (tid & 1) * 2;
    const uint32_t prodOff = (uint32_t)(pRow * ROWB + pCh * 16);

    const __half* aRowPtr = A + (m0 + pRow) * lda + pCh * 8;
    const __half* bRowPtr = B + (n0 + pRow) * ldb + pCh * 8;

    auto loadTile = [&](int kt, int stg) {
        const long long k0 = (long long)kt * TBK;
        long long kA, kB;
        if (kSplit > 0) {
            const long long kh = k0 / kSplit;
            const long long ko = k0 - kh * kSplit;
            kA = kh * aHead + ko;
            kB = kh * bHead + ko;
        } else {
            kA = k0; kB = k0;
        }
        const uint32_t ab = smBase + (uint32_t)stg * STGB + prodOff;
        const uint32_t bb = ab + BOFF;
#pragma unroll
        for (int c = 0; c < 2; ++c) {
            cp_async16(ab + c * 16, aRowPtr + kA + c * 8);
            cp_async16(bb + c * 16, bRowPtr + kB + c * 8);
        }
        asm volatile("cp.async.commit_group;\n" ::);
    };

    const int mat  = lane >> 3;
    const int row8 = lane & 7;
    uint32_t aOff[2], bOff[4];
#pragma unroll
    for (int i = 0; i < 2; ++i)
        aOff[i] = (uint32_t)((wm0 + i * 16 + (mat & 1) * 8 + row8) * ROWB
                             + (mat >> 1) * 16);
#pragma unroll
    for (int p = 0; p < 4; ++p)
        bOff[p] = (uint32_t)(BOFF + (wn0 + (2 * p + (mat >> 1)) * 8 + row8) * ROWB
                             + (mat & 1) * 16);

    float acc[2][8][4];
#pragma unroll
    for (int i = 0; i < 2; ++i)
#pragma unroll
        for (int j = 0; j < 8; ++j)
#pragma unroll
            for (int r = 0; r < 4; ++r) acc[i][j][r] = 0.f;

    const int nIter = K / TBK;
    loadTile(0, 0);
    if (nIter > 1) loadTile(1, 1);

    int stg = 0;
    for (int kt = 0; kt < nIter; ++kt) {
        if (kt + 1 < nIter) {
            asm volatile("cp.async.wait_group 1;\n" ::);
        } else {
            asm volatile("cp.async.wait_group 0;\n" ::);
        }
        __syncthreads();

        if (kt + 2 < nIter) {
            int ns = stg + 2; if (ns >= NSTG) ns -= NSTG;
            loadTile(kt + 2, ns);
        }

        const uint32_t base = smBase + (uint32_t)stg * STGB;
#pragma unroll
        for (int ks = 0; ks < 2; ++ks) {
            const uint32_t ksb = base + ks * 32;
            uint32_t af[2][4];
#pragma unroll
            for (int i = 0; i < 2; ++i)
                ldmatrix_x4(af[i][0], af[i][1], af[i][2], af[i][3], ksb + aOff[i]);
            uint32_t bf[8][2];
#pragma unroll
            for (int p = 0; p < 4; ++p)
                ldmatrix_x4(bf[2 * p][0], bf[2 * p][1],
                            bf[2 * p + 1][0], bf[2 * p + 1][1], ksb + bOff[p]);
#pragma unroll
            for (int i = 0; i < 2; ++i) {
#pragma unroll
                for (int j = 0; j < 8; ++j) {
                    asm volatile(
                        "mma.sync.aligned.m16n8k16.row.col.f32.f16.f16.f32 "
                        "{%0,%1,%2,%3}, {%4,%5,%6,%7}, {%8,%9}, {%0,%1,%2,%3};"
                        : "+f"(acc[i][j][0]), "+f"(acc[i][j][1]),
                          "+f"(acc[i][j][2]), "+f"(acc[i][j][3])
                        : "r"(af[i][0]), "r"(af[i][1]), "r"(af[i][2]), "r"(af[i][3]),
                          "r"(bf[j][0]), "r"(bf[j][1]));
                }
            }
        }
        ++stg; if (stg == NSTG) stg = 0;
    }

    const long long cBase = (long long)z * cHead;
#pragma unroll
    for (int i = 0; i < 2; ++i) {
        const long long r0 = m0 + wm0 + i * 16 + g;
#pragma unroll
        for (int j = 0; j < 8; ++j) {
            const long long cc = n0 + wn0 + j * 8 + 2 * tg;
            float b0 = 0.f, b1 = 0.f;
            if (bias) { b0 = bias[cc]; b1 = bias[cc + 1]; }
            float v00 = acc[i][j][0] + b0, v01 = acc[i][j][1] + b1;
            float v10 = acc[i][j][2] + b0, v11 = acc[i][j][3] + b1;
            if (outHalf) {
                __half* C = (__half*)Cv + cBase;
                __half2 h0 = __floats2half2_rn(v00, v01);
                __half2 h1 = __floats2half2_rn(v10, v11);
                *reinterpret_cast<__half2*>(C + r0 * ldc + cc) = h0;
                *reinterpret_cast<__half2*>(C + (r0 + 8) * ldc + cc) = h1;
            } else {
                float* C = (float*)Cv + cBase;
                *reinterpret_cast<float2*>(C + r0 * ldc + cc) = make_float2(v00, v01);
                *reinterpret_cast<float2*>(C + (r0 + 8) * ldc + cc) = make_float2(v10, v11);
            }
        }
    }
}

// ---------------------------------------------------------------------------
// In-place fp16 row softmax with ex2.approx.f16x2 (identical to R8).
// ---------------------------------------------------------------------------
template <int ROWLEN>
__global__ void __launch_bounds__(ROWLEN / 4) softmax_h(__half* __restrict__ data)
{
    constexpr int THREADS = ROWLEN / 4;
    constexpr int NW = THREADS / 32;
    const long long row = blockIdx.x;
    uint2* p = reinterpret_cast<uint2*>(data + row * (long long)ROWLEN);
    uint2 u = p[threadIdx.x];

    __half2 h0 = *reinterpret_cast<__half2*>(&u.x);
    __half2 h1 = *reinterpret_cast<__half2*>(&u.y);
    float2 f0 = __half22float2(h0);
    float2 f1 = __half22float2(h1);

    const int warp = threadIdx.x >> 5;
    const int lane = threadIdx.x & 31;
    __shared__ float sred[NW];

    float mx = fmaxf(fmaxf(f0.x, f0.y), fmaxf(f1.x, f1.y));
    mx = warpMax(mx);
    if (lane == 0) sred[warp] = mx;
    __syncthreads();
    if (warp == 0) {
        float t = (lane < NW) ? sred[lane] : -3.4e38f;
        t = warpMax(t);
        if (lane == 0) sred[0] = t;
    }
    __syncthreads();
    mx = sred[0];
    __syncthreads();

    const float L2E = 1.44269504f;
    __half2 a0 = __floats2half2_rn((f0.x - mx) * L2E, (f0.y - mx) * L2E);
    __half2 a1 = __floats2half2_rn((f1.x - mx) * L2E, (f1.y - mx) * L2E);
    uint32_t e0 = ex2_f16x2(*reinterpret_cast<uint32_t*>(&a0));
    uint32_t e1 = ex2_f16x2(*reinterpret_cast<uint32_t*>(&a1));
    float2 E0 = __half22float2(*reinterpret_cast<__half2*>(&e0));
    float2 E1 = __half22float2(*reinterpret_cast<__half2*>(&e1));

    float s = E0.x + E0.y + E1.x + E1.y;
    s = warpSum(s);
    if (lane == 0) sred[warp] = s;
    __syncthreads();
    if (warp == 0) {
        float t = (lane < NW) ? sred[lane] : 0.f;
        t = warpSum(t);
        if (lane == 0) sred[0] = t;
    }
    __syncthreads();
    const float inv = 1.0f / sred[0];

    __half2 w0 = __floats2half2_rn(E0.x * inv, E0.y * inv);
    __half2 w1 = __floats2half2_rn(E1.x * inv, E1.y * inv);
    uint2 o;
    o.x = *reinterpret_cast<uint32_t*>(&w0);
    o.y = *reinterpret_cast<uint32_t*>(&w1);
    p[threadIdx.x] = o;
}

// ---------------------------------------------------------------------------
// Launch: 3-stream DAG (graph-capturable fork/join via events)
// ---------------------------------------------------------------------------
extern "C" void kernel_launch(void* const* d_in, const int* in_sizes, int n_in,
                              void* d_out, int out_size)
{
    const float* k_in = (const float*)d_in[0];   // [N, O]
    const float* mems = (const float*)d_in[1];   // [H, M, D]
    const float* Wk   = (const float*)d_in[2];   // [H, O, D]
    const float* bk   = (const float*)d_in[3];   // [H, O]
    const float* Wv   = (const float*)d_in[4];   // [H, O, D]
    const float* bv   = (const float*)d_in[5];   // [H, O]
    const float* Wf   = (const float*)d_in[6];   // [O, H*O]
    const float* bf   = (const float*)d_in[7];   // [O]
    float* out = (float*)d_out;                  // [N, O]

    cudaFuncSetAttribute(gemm_nt_f16,
                         cudaFuncAttributeMaxDynamicSharedMemorySize, SMEM_DYN);

    // One-time infra (streams/events reused across calls; no device memory).
    static cudaStream_t sB = nullptr, sC = nullptr;
    static cudaEvent_t eFork, eMems, eK, eWf, e3b;
    if (sB == nullptr) {
        cudaStreamCreateWithFlags(&sB, cudaStreamNonBlocking);
        cudaStreamCreateWithFlags(&sC, cudaStreamNonBlocking);
        cudaEventCreateWithFlags(&eFork, cudaEventDisableTiming);
        cudaEventCreateWithFlags(&eMems, cudaEventDisableTiming);
        cudaEventCreateWithFlags(&eK,    cudaEventDisableTiming);
        cudaEventCreateWithFlags(&eWf,   cudaEventDisableTiming);
        cudaEventCreateWithFlags(&e3b,   cudaEventDisableTiming);
    }

    __half *kh, *memsh, *Wkh, *Wvh, *Wfh, *memkeyh, *memvalh, *GTh, *atth;
    cudaGetSymbolAddress((void**)&kh,      g_kh);
    cudaGetSymbolAddress((void**)&memsh,   g_memsh);
    cudaGetSymbolAddress((void**)&Wkh,     g_Wkh);
    cudaGetSymbolAddress((void**)&Wvh,     g_Wvh);
    cudaGetSymbolAddress((void**)&Wfh,     g_Wfh);
    cudaGetSymbolAddress((void**)&memkeyh, g_memkeyh);
    cudaGetSymbolAddress((void**)&memvalh, g_memvalh);
    cudaGetSymbolAddress((void**)&GTh,     g_GTh);
    cudaGetSymbolAddress((void**)&atth,    g_atth);

    const long long MD = (long long)M_ * D_;
    const long long OD = (long long)O_ * D_;
    const long long MO = (long long)M_ * O_;
    const long long NM = (long long)N_ * M_;

    auto cvtOn = [&](cudaStream_t s, const float* src, __half* dst, long long n) {
        int n8 = (int)(n / 8);
        cvt_f32_f16<<<(n8 + 255) / 256, 256, 0, s>>>(
            (const float4*)src, (uint2*)dst, n8);
    };

    // ---- fork ----
    cudaEventRecord(eFork, 0);
    cudaStreamWaitEvent(sB, eFork, 0);
    cudaStreamWaitEvent(sC, eFork, 0);

    // sC: cvt k (needed by GEMM4), then cvt Wf (needed by GEMM3b on sB)
    cvtOn(sC, k_in, kh, (long long)N_ * O_);
    cudaEventRecord(eK, sC);
    cvtOn(sC, Wf, Wfh, (long long)O_ * H_ * O_);
    cudaEventRecord(eWf, sC);

    // spine: cvt mems, cvt Wk
    cvtOn(0, mems, memsh, (long long)H_ * M_ * D_);
    cudaEventRecord(eMems, 0);
    cvtOn(0, Wk, Wkh, (long long)H_ * O_ * D_);

    // sB: cvt Wv, then GEMM2 (mem_val), then GEMM3b (GT)
    cvtOn(sB, Wv, Wvh, (long long)H_ * O_ * D_);
    cudaStreamWaitEvent(sB, eMems, 0);
    {
        dim3 grid(O_ / TBN, M_ / TBM, H_);
        gemm_nt_f16<<<grid, 256, SMEM_DYN, sB>>>(memsh, MD, D_, Wvh, OD, D_,
                                                 memvalh, MO, O_, bv, O_, D_, 0, 1);
    }
    cudaStreamWaitEvent(sB, eWf, 0);
    {
        dim3 grid(M_ / TBN, O_ / TBM, H_);
        gemm_nt_f16<<<grid, 256, SMEM_DYN, sB>>>(Wfh, O_, (long long)H_ * O_,
                                                 memvalh, MO, O_,
                                                 GTh, MO, M_, nullptr, 0, O_, 0, 1);
    }
    cudaEventRecord(e3b, sB);

    // spine: GEMM1 (key logits) -> softmax3 -> GEMM4 -> softmax5
    {
        dim3 grid(O_ / TBN, M_ / TBM, H_);
        gemm_nt_f16<<<grid, 256, SMEM_DYN>>>(memsh, MD, D_, Wkh, OD, D_,
                                             memkeyh, MO, O_, bk, O_, D_, 0, 1);
    }
    softmax_h<512><<<H_ * M_, 128>>>(memkeyh);

    cudaStreamWaitEvent(0, eK, 0);
    {
        dim3 grid(M_ / TBN, N_ / TBM, H_);
        gemm_nt_f16<<<grid, 256, SMEM_DYN>>>(kh, 0, O_, memkeyh, MO, O_,
                                             atth, NM, M_, nullptr, 0, O_, 0, 1);
    }
    softmax_h<1024><<<H_ * N_, 256>>>(atth);

    // join: GEMM6 needs GT (sB chain, which also carries sC's eWf)
    cudaStreamWaitEvent(0, e3b, 0);
    {
        dim3 grid(O_ / TBN, N_ / TBM, 1);
        gemm_nt_f16<<<grid, 256, SMEM_DYN>>>(atth, NM, M_, GTh, MO, M_,
                                             out, 0, O_, bf, 0, H_ * M_, M_, 0);
    }
}